// round 6
// baseline (speedup 1.0000x reference)
#include <cuda_runtime.h>
#include <cstdint>

#define FULL 0xffffffffu

constexpr int NN   = 50000;
constexpr int FEA  = 213;
constexpr int H1   = 12, C1 = 16, D1 = 192;
constexpr int H2   = 8,  C2 = 8,  D2 = 64;
constexpr int PAIRS = 16384;
constexpr int EMAX = 800000;
constexpr int ETOTMAX = EMAX + NN;

// ---------------- device scratch (static, no runtime alloc) ----------------
__device__ float g_h1[NN * D1];
__device__ float g_x1[NN * D1];
__device__ float g_h2[NN * D2];
__device__ float g_as1[NN * H1];
__device__ float g_ad1[NN * H1];
__device__ float g_as2[NN * H2];
__device__ float g_ad2[NN * H2];
__device__ int   g_deg[NN];
__device__ int   g_cursor[NN];
__device__ int   g_rowptr[NN + 1];
__device__ int   g_col[ETOTMAX];

__device__ __forceinline__ float leaky(float x) { return x > 0.f ? x : 0.2f * x; }

// ---------------- CSR build ----------------
__global__ void k_init_deg() {
    int i = blockIdx.x * blockDim.x + threadIdx.x;
    if (i < NN) { g_deg[i] = 0; g_cursor[i] = 0; }
}

__global__ void k_count(const int* __restrict__ ei, int E, int ETOT) {
    int i = blockIdx.x * blockDim.x + threadIdx.x;
    if (i >= ETOT) return;
    int dst = (i < E) ? ei[E + i] : (i - E);
    atomicAdd(&g_deg[dst], 1);
}

__global__ void k_scan() {  // single block, 1024 threads
    __shared__ int s[1024];
    int t = threadIdx.x;
    const int chunk = (NN + 1023) / 1024;
    int start = t * chunk;
    int end = start + chunk; if (end > NN) end = NN; if (start > NN) start = NN;
    int sum = 0;
    for (int i = start; i < end; i++) sum += g_deg[i];
    s[t] = sum;
    __syncthreads();
    for (int off = 1; off < 1024; off <<= 1) {
        int v = 0;
        if (t >= off) v = s[t - off];
        __syncthreads();
        s[t] += v;
        __syncthreads();
    }
    int run = s[t] - sum;  // exclusive prefix
    for (int i = start; i < end; i++) { g_rowptr[i] = run; run += g_deg[i]; }
    if (t == 1023) g_rowptr[NN] = s[1023];
}

__global__ void k_scatter(const int* __restrict__ ei, int E, int ETOT) {
    int i = blockIdx.x * blockDim.x + threadIdx.x;
    if (i >= ETOT) return;
    int src, dst;
    if (i < E) { src = ei[i]; dst = ei[E + i]; }
    else       { src = dst = i - E; }
    int pos = atomicAdd(&g_cursor[dst], 1);
    g_col[g_rowptr[dst] + pos] = src;
}

// ---------------- 3xTF32 tensor-core GEMM (pre-split in smem) ----------------
__device__ __forceinline__ uint32_t f2tf(float x) {
    uint32_t r;
    asm("cvt.rna.tf32.f32 %0, %1;" : "=r"(r) : "f"(x));
    return r;
}
__device__ __forceinline__ float2 split2(float x) {
    uint32_t big = f2tf(x);
    uint32_t sml = f2tf(x - __uint_as_float(big));
    return make_float2(__uint_as_float(big), __uint_as_float(sml));
}
__device__ __forceinline__ void mma_tf32(float* c, const uint32_t* a, const uint32_t* b) {
    asm volatile(
        "mma.sync.aligned.m16n8k8.row.col.f32.tf32.tf32.f32 "
        "{%0,%1,%2,%3}, {%4,%5,%6,%7}, {%8,%9}, {%0,%1,%2,%3};"
        : "+f"(c[0]), "+f"(c[1]), "+f"(c[2]), "+f"(c[3])
        : "r"(a[0]), "r"(a[1]), "r"(a[2]), "r"(a[3]), "r"(b[0]), "r"(b[1]));
}

// C[M,Nc] = A[M,K] @ B[K,Nc]. 256 threads = 8 warps (4 along M x 2 along N).
// Block tile 128x64; warp tile 32x32. Smem holds pre-split tf32 (big,small)
// pairs interleaved; inner loop = LDS.64 + MMA only (no cvt).
// Padding of 16 floats makes k-stride == 64B mod 128 -> 2-way LDS max.
template <int BM, int BN, int BK>
__global__ void __launch_bounds__(256)
k_gemm_tc(const float* __restrict__ A, const float* __restrict__ B,
          float* __restrict__ Cm, int M, int K, int Nc) {
    __shared__ __align__(16) float As2[2][BK][2 * BM + 16];
    __shared__ __align__(16) float Bs2[2][BK][2 * BN + 16];
    constexpr int ALD = BM * BK / 256;   // 8
    constexpr int BLD = BK * BN / 256;   // 4
    int t = threadIdx.x;
    int lane = t & 31, wid = t >> 5;
    int wm = wid & 3, wn = wid >> 2;     // warp coords: 4 x 2
    int bm = blockIdx.y * BM, bn = blockIdx.x * BN;
    float acc[2][4][4] = {};
    float ra[ALD], rb[BLD];

    // prologue: tile 0, convert at store
    #pragma unroll
    for (int u = 0; u < ALD; u++) {
        int i = t + 256 * u;
        int r = i / BK, c = i % BK;
        int row = bm + r;
        float v = (row < M && c < K) ? A[(long)row * K + c] : 0.f;
        *(float2*)&As2[0][c][2 * r] = split2(v);
    }
    #pragma unroll
    for (int u = 0; u < BLD; u++) {
        int i = t + 256 * u;
        int r = i / BN, c = i % BN;
        float v = (r < K) ? B[(long)r * Nc + bn + c] : 0.f;
        *(float2*)&Bs2[0][r][2 * c] = split2(v);
    }
    __syncthreads();

    int nTiles = (K + BK - 1) / BK;
    for (int tile = 0; tile < nTiles; tile++) {
        int buf = tile & 1;
        int k0n = (tile + 1) * BK;
        if (tile + 1 < nTiles) {
            #pragma unroll
            for (int u = 0; u < ALD; u++) {
                int i = t + 256 * u;
                int r = i / BK, c = i % BK;
                int row = bm + r, kk = k0n + c;
                ra[u] = (row < M && kk < K) ? A[(long)row * K + kk] : 0.f;
            }
            #pragma unroll
            for (int u = 0; u < BLD; u++) {
                int i = t + 256 * u;
                int r = i / BN, c = i % BN;
                int kk = k0n + r;
                rb[u] = (kk < K) ? B[(long)kk * Nc + bn + c] : 0.f;
            }
        }
        // compute: BK/8 k-steps; pure LDS + MMA
        #pragma unroll
        for (int ks = 0; ks < BK / 8; ks++) {
            int kc = ks * 8 + (lane & 3);
            uint32_t abig[2][4], asml[2][4];
            #pragma unroll
            for (int mt = 0; mt < 2; mt++) {
                int row = wm * 32 + mt * 16 + (lane >> 2);
                float2 p0 = *(const float2*)&As2[buf][kc][2 * row];
                float2 p1 = *(const float2*)&As2[buf][kc][2 * (row + 8)];
                float2 p2 = *(const float2*)&As2[buf][kc + 4][2 * row];
                float2 p3 = *(const float2*)&As2[buf][kc + 4][2 * (row + 8)];
                abig[mt][0] = __float_as_uint(p0.x); asml[mt][0] = __float_as_uint(p0.y);
                abig[mt][1] = __float_as_uint(p1.x); asml[mt][1] = __float_as_uint(p1.y);
                abig[mt][2] = __float_as_uint(p2.x); asml[mt][2] = __float_as_uint(p2.y);
                abig[mt][3] = __float_as_uint(p3.x); asml[mt][3] = __float_as_uint(p3.y);
            }
            uint32_t bbig[4][2], bsml[4][2];
            #pragma unroll
            for (int nt = 0; nt < 4; nt++) {
                int col = wn * 32 + nt * 8 + (lane >> 2);
                float2 q0 = *(const float2*)&Bs2[buf][kc][2 * col];
                float2 q1 = *(const float2*)&Bs2[buf][kc + 4][2 * col];
                bbig[nt][0] = __float_as_uint(q0.x); bsml[nt][0] = __float_as_uint(q0.y);
                bbig[nt][1] = __float_as_uint(q1.x); bsml[nt][1] = __float_as_uint(q1.y);
            }
            #pragma unroll
            for (int mt = 0; mt < 2; mt++)
                #pragma unroll
                for (int nt = 0; nt < 4; nt++) {
                    mma_tf32(acc[mt][nt], asml[mt], bbig[nt]);
                    mma_tf32(acc[mt][nt], abig[mt], bsml[nt]);
                    mma_tf32(acc[mt][nt], abig[mt], bbig[nt]);
                }
        }
        if (tile + 1 < nTiles) {
            __syncthreads();
            int nb = buf ^ 1;
            #pragma unroll
            for (int u = 0; u < ALD; u++) {
                int i = t + 256 * u;
                *(float2*)&As2[nb][i % BK][2 * (i / BK)] = split2(ra[u]);
            }
            #pragma unroll
            for (int u = 0; u < BLD; u++) {
                int i = t + 256 * u;
                *(float2*)&Bs2[nb][i / BN][2 * (i % BN)] = split2(rb[u]);
            }
            __syncthreads();
        }
    }
    // epilogue
    #pragma unroll
    for (int mt = 0; mt < 2; mt++) {
        int row0 = bm + wm * 32 + mt * 16 + (lane >> 2);
        #pragma unroll
        for (int nt = 0; nt < 4; nt++) {
            int col = bn + wn * 32 + nt * 8 + 2 * (lane & 3);
            if (row0 < M)
                *(float2*)&Cm[(long)row0 * Nc + col] =
                    make_float2(acc[mt][nt][0], acc[mt][nt][1]);
            if (row0 + 8 < M)
                *(float2*)&Cm[(long)(row0 + 8) * Nc + col] =
                    make_float2(acc[mt][nt][2], acc[mt][nt][3]);
        }
    }
}

// ---------------- attention scores a_src, a_dst (float4 loads) ----------------
template <int H, int C>
__global__ void k_attn(const float* __restrict__ h, const float* __restrict__ aS,
                       const float* __restrict__ aD, float* __restrict__ s_,
                       float* __restrict__ d_) {
    int i = blockIdx.x * blockDim.x + threadIdx.x;
    if (i >= NN * H) return;
    int n = i / H, hh = i % H;
    const float4* hp = (const float4*)(h + (long)n * H * C + hh * C);
    const float4* sp = (const float4*)(aS + hh * C);
    const float4* dp = (const float4*)(aD + hh * C);
    float s = 0.f, d = 0.f;
    #pragma unroll
    for (int c = 0; c < C / 4; c++) {
        float4 v = hp[c], a = sp[c], b = dp[c];
        s += v.x * a.x + v.y * a.y + v.z * a.z + v.w * a.w;
        d += v.x * b.x + v.y * b.y + v.z * b.z + v.w * b.w;
    }
    s_[i] = s; d_[i] = d;
}

// ---------------- warp-per-node segment-softmax aggregation (float2) --------
template <int H, int C>
__global__ void k_agg(const float* __restrict__ h, const float* __restrict__ as_,
                      const float* __restrict__ ad_, const float* __restrict__ bias,
                      float* __restrict__ out) {
    constexpr int D = H * C;
    constexpr int PER2 = D / 64;
    int warp = (blockIdx.x * blockDim.x + threadIdx.x) >> 5;
    int lane = threadIdx.x & 31;
    if (warp >= NN) return;
    int node = warp;
    int r0 = g_rowptr[node];
    int r1 = g_rowptr[node + 1];

    float adv = (lane < H) ? ad_[node * H + lane] : 0.f;

    float2 acc[PER2];
    #pragma unroll
    for (int i = 0; i < PER2; i++) acc[i] = make_float2(0.f, 0.f);
    float denom = 0.f;
    int j = r0;
    for (; j + 3 < r1; j += 4) {
        int s0 = g_col[j], s1 = g_col[j + 1], s2 = g_col[j + 2], s3 = g_col[j + 3];
        float w0 = 0.f, w1 = 0.f, w2 = 0.f, w3 = 0.f;
        if (lane < H) {
            w0 = __expf(leaky(__ldg(as_ + (long)s0 * H + lane) + adv));
            w1 = __expf(leaky(__ldg(as_ + (long)s1 * H + lane) + adv));
            w2 = __expf(leaky(__ldg(as_ + (long)s2 * H + lane) + adv));
            w3 = __expf(leaky(__ldg(as_ + (long)s3 * H + lane) + adv));
            denom += (w0 + w1) + (w2 + w3);
        }
        const float* h0 = h + (long)s0 * D;
        const float* h1 = h + (long)s1 * D;
        const float* h2 = h + (long)s2 * D;
        const float* h3 = h + (long)s3 * D;
        #pragma unroll
        for (int i = 0; i < PER2; i++) {
            int k2 = 2 * lane + 64 * i;
            int sl = k2 / C;
            float wa = __shfl_sync(FULL, w0, sl);
            float wb = __shfl_sync(FULL, w1, sl);
            float wc = __shfl_sync(FULL, w2, sl);
            float wd = __shfl_sync(FULL, w3, sl);
            float2 v0 = *(const float2*)&h0[k2];
            float2 v1 = *(const float2*)&h1[k2];
            float2 v2 = *(const float2*)&h2[k2];
            float2 v3 = *(const float2*)&h3[k2];
            acc[i].x += wa * v0.x + wb * v1.x + wc * v2.x + wd * v3.x;
            acc[i].y += wa * v0.y + wb * v1.y + wc * v2.y + wd * v3.y;
        }
    }
    for (; j < r1; j++) {
        int s0 = g_col[j];
        float w0 = 0.f;
        if (lane < H) {
            w0 = __expf(leaky(__ldg(as_ + (long)s0 * H + lane) + adv));
            denom += w0;
        }
        const float* h0 = h + (long)s0 * D;
        #pragma unroll
        for (int i = 0; i < PER2; i++) {
            int k2 = 2 * lane + 64 * i;
            float wa = __shfl_sync(FULL, w0, k2 / C);
            float2 v0 = *(const float2*)&h0[k2];
            acc[i].x += wa * v0.x;
            acc[i].y += wa * v0.y;
        }
    }

    float rden = __frcp_rn(denom);
    #pragma unroll
    for (int i = 0; i < PER2; i++) {
        int k2 = 2 * lane + 64 * i;
        float rk = __shfl_sync(FULL, rden, k2 / C);
        float2 bv = *(const float2*)&bias[k2];
        float vx = acc[i].x * rk + bv.x;
        float vy = acc[i].y * rk + bv.y;
        vx = vx > 0.f ? vx : __expf(vx) - 1.f;
        vy = vy > 0.f ? vy : __expf(vy) - 1.f;
        *(float2*)&out[(long)node * D + k2] = make_float2(vx, vy);
    }
}

// ---------------- pair scoring head ----------------
__global__ void k_pair(const float* __restrict__ x, const int* __restrict__ n1,
                       const int* __restrict__ n2, const float* __restrict__ linW,
                       const float* __restrict__ linb, float* __restrict__ y) {
    int warp = (blockIdx.x * blockDim.x + threadIdx.x) >> 5;
    int lane = threadIdx.x & 31;
    if (warp >= PAIRS) return;
    int a = n1[warp], b = n2[warp];
    float p0 = 0.f, p1 = 0.f;
    #pragma unroll
    for (int i = 0; i < 4; i++) {
        int k = lane + 32 * i;
        float xv = (k < D2) ? x[(long)a * D2 + k] : x[(long)b * D2 + (k - D2)];
        p0 += xv * linW[k * 2 + 0];
        p1 += xv * linW[k * 2 + 1];
    }
    #pragma unroll
    for (int off = 16; off; off >>= 1) {
        p0 += __shfl_xor_sync(FULL, p0, off);
        p1 += __shfl_xor_sync(FULL, p1, off);
    }
    if (lane == 0) {
        float z0 = p0 + linb[0], z1 = p1 + linb[1];
        y[warp * 2 + 0] = 1.f / (1.f + __expf(-z0));
        y[warp * 2 + 1] = 1.f / (1.f + __expf(-z1));
    }
}

// ---------------- launcher with fork/join stream overlap ----------------
extern "C" void kernel_launch(void* const* d_in, const int* in_sizes, int n_in,
                              void* d_out, int out_size) {
    const float* features = (const float*)d_in[0];
    const int*   edge_index = (const int*)d_in[1];
    const int*   n1 = (const int*)d_in[2];
    const int*   n2 = (const int*)d_in[3];
    const float* W1 = (const float*)d_in[4];
    const float* attS1 = (const float*)d_in[5];
    const float* attD1 = (const float*)d_in[6];
    const float* b1 = (const float*)d_in[7];
    const float* W2 = (const float*)d_in[8];
    const float* attS2 = (const float*)d_in[9];
    const float* attD2 = (const float*)d_in[10];
    const float* b2 = (const float*)d_in[11];
    const float* linW = (const float*)d_in[12];
    const float* linb = (const float*)d_in[13];

    float* out  = (float*)d_out;
    float* y    = out;               // y_pred: [PAIRS, 2]
    float* xout = out + PAIRS * 2;   // x:      [NN, D2]

    int E = in_sizes[1] / 2;
    int ETOT = E + NN;

    float *p_h1, *p_x1, *p_h2, *p_as1, *p_ad1, *p_as2, *p_ad2;
    cudaGetSymbolAddress((void**)&p_h1, g_h1);
    cudaGetSymbolAddress((void**)&p_x1, g_x1);
    cudaGetSymbolAddress((void**)&p_h2, g_h2);
    cudaGetSymbolAddress((void**)&p_as1, g_as1);
    cudaGetSymbolAddress((void**)&p_ad1, g_ad1);
    cudaGetSymbolAddress((void**)&p_as2, g_as2);
    cudaGetSymbolAddress((void**)&p_ad2, g_ad2);

    static cudaStream_t s2 = nullptr;
    static cudaEvent_t evFork = nullptr, evJoin = nullptr;
    if (!s2) {
        cudaStreamCreateWithFlags(&s2, cudaStreamNonBlocking);
        cudaEventCreateWithFlags(&evFork, cudaEventDisableTiming);
        cudaEventCreateWithFlags(&evJoin, cudaEventDisableTiming);
    }

    // fork: CSR build on s2 overlaps GEMM1 + attn1 on main stream
    cudaEventRecord(evFork, 0);
    cudaStreamWaitEvent(s2, evFork, 0);

    k_init_deg<<<(NN + 255) / 256, 256, 0, s2>>>();
    k_count<<<(ETOT + 255) / 256, 256, 0, s2>>>(edge_index, E, ETOT);
    k_scan<<<1, 1024, 0, s2>>>();
    k_scatter<<<(ETOT + 255) / 256, 256, 0, s2>>>(edge_index, E, ETOT);
    cudaEventRecord(evJoin, s2);

    {
        dim3 grid(D1 / 64, (NN + 127) / 128);
        k_gemm_tc<128, 64, 16><<<grid, 256>>>(features, W1, p_h1, NN, FEA, D1);
    }
    k_attn<H1, C1><<<(NN * H1 + 255) / 256, 256>>>(p_h1, attS1, attD1, p_as1, p_ad1);

    cudaStreamWaitEvent(0, evJoin, 0);

    k_agg<H1, C1><<<(NN * 32 + 255) / 256, 256>>>(p_h1, p_as1, p_ad1, b1, p_x1);

    // Layer 2
    {
        dim3 grid(D2 / 64, (NN + 127) / 128);
        k_gemm_tc<128, 64, 16><<<grid, 256>>>(p_x1, W2, p_h2, NN, D1, D2);
    }
    k_attn<H2, C2><<<(NN * H2 + 255) / 256, 256>>>(p_h2, attS2, attD2, p_as2, p_ad2);
    k_agg<H2, C2><<<(NN * 32 + 255) / 256, 256>>>(p_h2, p_as2, p_ad2, b2, xout);

    // Pair head
    k_pair<<<(PAIRS * 32 + 255) / 256, 256>>>(xout, n1, n2, linW, linb, y);
}

// round 7
// speedup vs baseline: 1.1970x; 1.1970x over previous
#include <cuda_runtime.h>
#include <cstdint>

#define FULL 0xffffffffu

constexpr int NN   = 50000;
constexpr int FEA  = 213;
constexpr int H1   = 12, C1 = 16, D1 = 192;
constexpr int H2   = 8,  C2 = 8,  D2 = 64;
constexpr int PAIRS = 16384;
constexpr int EMAX = 800000;
constexpr int ETOTMAX = EMAX + NN;
constexpr int NHALF = 25088;   // node split for agg1/GEMM2 pipelining (mult of 128)

// ---------------- device scratch (static, no runtime alloc) ----------------
__device__ float g_h1[NN * D1];
__device__ float g_x1[NN * D1];
__device__ float g_h2[NN * D2];
__device__ float g_as1[NN * H1];
__device__ float g_ad1[NN * H1];
__device__ float g_as2[NN * H2];
__device__ float g_ad2[NN * H2];
__device__ int   g_deg[NN];
__device__ int   g_cursor[NN];
__device__ int   g_rowptr[NN + 1];
__device__ int   g_col[ETOTMAX];

__device__ __forceinline__ float leaky(float x) { return x > 0.f ? x : 0.2f * x; }

// ---------------- CSR build ----------------
__global__ void k_init_deg() {
    int i = blockIdx.x * blockDim.x + threadIdx.x;
    if (i < NN) { g_deg[i] = 0; g_cursor[i] = 0; }
}

__global__ void k_count(const int* __restrict__ ei, int E, int ETOT) {
    int i = blockIdx.x * blockDim.x + threadIdx.x;
    if (i >= ETOT) return;
    int dst = (i < E) ? ei[E + i] : (i - E);
    atomicAdd(&g_deg[dst], 1);
}

__global__ void k_scan() {  // single block, 1024 threads
    __shared__ int s[1024];
    int t = threadIdx.x;
    const int chunk = (NN + 1023) / 1024;
    int start = t * chunk;
    int end = start + chunk; if (end > NN) end = NN; if (start > NN) start = NN;
    int sum = 0;
    for (int i = start; i < end; i++) sum += g_deg[i];
    s[t] = sum;
    __syncthreads();
    for (int off = 1; off < 1024; off <<= 1) {
        int v = 0;
        if (t >= off) v = s[t - off];
        __syncthreads();
        s[t] += v;
        __syncthreads();
    }
    int run = s[t] - sum;  // exclusive prefix
    for (int i = start; i < end; i++) { g_rowptr[i] = run; run += g_deg[i]; }
    if (t == 1023) g_rowptr[NN] = s[1023];
}

__global__ void k_scatter(const int* __restrict__ ei, int E, int ETOT) {
    int i = blockIdx.x * blockDim.x + threadIdx.x;
    if (i >= ETOT) return;
    int src, dst;
    if (i < E) { src = ei[i]; dst = ei[E + i]; }
    else       { src = dst = i - E; }
    int pos = atomicAdd(&g_cursor[dst], 1);
    g_col[g_rowptr[dst] + pos] = src;
}

// ---------------- 3xTF32 tensor-core GEMM (B pre-split in smem) -------------
__device__ __forceinline__ uint32_t f2tf(float x) {
    uint32_t r;
    asm("cvt.rna.tf32.f32 %0, %1;" : "=r"(r) : "f"(x));
    return r;
}
__device__ __forceinline__ void split_tf32(float x, uint32_t& big, uint32_t& sml) {
    big = f2tf(x);
    sml = f2tf(x - __uint_as_float(big));
}
__device__ __forceinline__ float2 split2(float x) {
    uint32_t big = f2tf(x);
    uint32_t sml = f2tf(x - __uint_as_float(big));
    return make_float2(__uint_as_float(big), __uint_as_float(sml));
}
__device__ __forceinline__ void mma_tf32(float* c, const uint32_t* a, const uint32_t* b) {
    asm volatile(
        "mma.sync.aligned.m16n8k8.row.col.f32.tf32.tf32.f32 "
        "{%0,%1,%2,%3}, {%4,%5,%6,%7}, {%8,%9}, {%0,%1,%2,%3};"
        : "+f"(c[0]), "+f"(c[1]), "+f"(c[2]), "+f"(c[3])
        : "r"(a[0]), "r"(a[1]), "r"(a[2]), "r"(a[3]), "r"(b[0]), "r"(b[1]));
}

// C[M,Nc] = A[M,K] @ B[K,Nc]. 256 threads = 8 warps (4 along M x 2 along N).
// Block tile 128x64; warp tile 32x32. A stored fp32 in smem (split in regs,
// 2x redundancy); B stored pre-split (big,small) pairs (read by 4 warps each).
// Total smem ~34KB -> good occupancy. Double-buffered, register-staged.
template <int BM, int BN, int BK>
__global__ void __launch_bounds__(256)
k_gemm_tc(const float* __restrict__ A, const float* __restrict__ B,
          float* __restrict__ Cm, int M, int K, int Nc) {
    __shared__ __align__(16) float As[2][BK][BM + 4];
    __shared__ __align__(16) float Bs2[2][BK][2 * BN + 8];
    constexpr int ALD = BM * BK / 256;   // 8
    constexpr int BLD = BK * BN / 256;   // 4
    int t = threadIdx.x;
    int lane = t & 31, wid = t >> 5;
    int wm = wid & 3, wn = wid >> 2;
    int bm = blockIdx.y * BM, bn = blockIdx.x * BN;
    float acc[2][4][4] = {};
    float ra[ALD], rb[BLD];

    // prologue: tile 0
    #pragma unroll
    for (int u = 0; u < ALD; u++) {
        int i = t + 256 * u;
        int r = i / BK, c = i % BK;
        int row = bm + r;
        As[0][c][r] = (row < M && c < K) ? A[(long)row * K + c] : 0.f;
    }
    #pragma unroll
    for (int u = 0; u < BLD; u++) {
        int i = t + 256 * u;
        int r = i / BN, c = i % BN;
        float v = (r < K) ? B[(long)r * Nc + bn + c] : 0.f;
        *(float2*)&Bs2[0][r][2 * c] = split2(v);
    }
    __syncthreads();

    int nTiles = (K + BK - 1) / BK;
    for (int tile = 0; tile < nTiles; tile++) {
        int buf = tile & 1;
        int k0n = (tile + 1) * BK;
        if (tile + 1 < nTiles) {
            #pragma unroll
            for (int u = 0; u < ALD; u++) {
                int i = t + 256 * u;
                int r = i / BK, c = i % BK;
                int row = bm + r, kk = k0n + c;
                ra[u] = (row < M && kk < K) ? A[(long)row * K + kk] : 0.f;
            }
            #pragma unroll
            for (int u = 0; u < BLD; u++) {
                int i = t + 256 * u;
                int r = i / BN, c = i % BN;
                int kk = k0n + r;
                rb[u] = (kk < K) ? B[(long)kk * Nc + bn + c] : 0.f;
            }
        }
        #pragma unroll
        for (int ks = 0; ks < BK / 8; ks++) {
            int kc = ks * 8 + (lane & 3);
            uint32_t abig[2][4], asml[2][4];
            #pragma unroll
            for (int mt = 0; mt < 2; mt++) {
                int row = wm * 32 + mt * 16 + (lane >> 2);
                float a0 = As[buf][kc][row];
                float a1 = As[buf][kc][row + 8];
                float a2 = As[buf][kc + 4][row];
                float a3 = As[buf][kc + 4][row + 8];
                split_tf32(a0, abig[mt][0], asml[mt][0]);
                split_tf32(a1, abig[mt][1], asml[mt][1]);
                split_tf32(a2, abig[mt][2], asml[mt][2]);
                split_tf32(a3, abig[mt][3], asml[mt][3]);
            }
            uint32_t bbig[4][2], bsml[4][2];
            #pragma unroll
            for (int nt = 0; nt < 4; nt++) {
                int col = wn * 32 + nt * 8 + (lane >> 2);
                float2 q0 = *(const float2*)&Bs2[buf][kc][2 * col];
                float2 q1 = *(const float2*)&Bs2[buf][kc + 4][2 * col];
                bbig[nt][0] = __float_as_uint(q0.x); bsml[nt][0] = __float_as_uint(q0.y);
                bbig[nt][1] = __float_as_uint(q1.x); bsml[nt][1] = __float_as_uint(q1.y);
            }
            #pragma unroll
            for (int mt = 0; mt < 2; mt++)
                #pragma unroll
                for (int nt = 0; nt < 4; nt++) {
                    mma_tf32(acc[mt][nt], asml[mt], bbig[nt]);
                    mma_tf32(acc[mt][nt], abig[mt], bsml[nt]);
                    mma_tf32(acc[mt][nt], abig[mt], bbig[nt]);
                }
        }
        if (tile + 1 < nTiles) {
            __syncthreads();
            int nb = buf ^ 1;
            #pragma unroll
            for (int u = 0; u < ALD; u++) {
                int i = t + 256 * u;
                As[nb][i % BK][i / BK] = ra[u];
            }
            #pragma unroll
            for (int u = 0; u < BLD; u++) {
                int i = t + 256 * u;
                *(float2*)&Bs2[nb][i / BN][2 * (i % BN)] = split2(rb[u]);
            }
            __syncthreads();
        }
    }
    #pragma unroll
    for (int mt = 0; mt < 2; mt++) {
        int row0 = bm + wm * 32 + mt * 16 + (lane >> 2);
        #pragma unroll
        for (int nt = 0; nt < 4; nt++) {
            int col = bn + wn * 32 + nt * 8 + 2 * (lane & 3);
            if (row0 < M)
                *(float2*)&Cm[(long)row0 * Nc + col] =
                    make_float2(acc[mt][nt][0], acc[mt][nt][1]);
            if (row0 + 8 < M)
                *(float2*)&Cm[(long)(row0 + 8) * Nc + col] =
                    make_float2(acc[mt][nt][2], acc[mt][nt][3]);
        }
    }
}

// ---------------- attention scores a_src, a_dst (float4 loads) ----------------
template <int H, int C>
__global__ void k_attn(const float* __restrict__ h, const float* __restrict__ aS,
                       const float* __restrict__ aD, float* __restrict__ s_,
                       float* __restrict__ d_) {
    int i = blockIdx.x * blockDim.x + threadIdx.x;
    if (i >= NN * H) return;
    int n = i / H, hh = i % H;
    const float4* hp = (const float4*)(h + (long)n * H * C + hh * C);
    const float4* sp = (const float4*)(aS + hh * C);
    const float4* dp = (const float4*)(aD + hh * C);
    float s = 0.f, d = 0.f;
    #pragma unroll
    for (int c = 0; c < C / 4; c++) {
        float4 v = hp[c], a = sp[c], b = dp[c];
        s += v.x * a.x + v.y * a.y + v.z * a.z + v.w * a.w;
        d += v.x * b.x + v.y * b.y + v.z * b.z + v.w * b.w;
    }
    s_[i] = s; d_[i] = d;
}

// ---------------- warp-per-node segment-softmax aggregation (float2) --------
// Processes nodes [n0, n0+cnt). Max-free softmax, fused single pass, x4 unroll.
template <int H, int C>
__global__ void k_agg(const float* __restrict__ h, const float* __restrict__ as_,
                      const float* __restrict__ ad_, const float* __restrict__ bias,
                      float* __restrict__ out, int n0, int cnt) {
    constexpr int D = H * C;
    constexpr int PER2 = D / 64;
    int warp = (blockIdx.x * blockDim.x + threadIdx.x) >> 5;
    int lane = threadIdx.x & 31;
    if (warp >= cnt) return;
    int node = n0 + warp;
    int r0 = g_rowptr[node];
    int r1 = g_rowptr[node + 1];

    float adv = (lane < H) ? ad_[node * H + lane] : 0.f;

    float2 acc[PER2];
    #pragma unroll
    for (int i = 0; i < PER2; i++) acc[i] = make_float2(0.f, 0.f);
    float denom = 0.f;
    int j = r0;
    for (; j + 3 < r1; j += 4) {
        int s0 = g_col[j], s1 = g_col[j + 1], s2 = g_col[j + 2], s3 = g_col[j + 3];
        float w0 = 0.f, w1 = 0.f, w2 = 0.f, w3 = 0.f;
        if (lane < H) {
            w0 = __expf(leaky(__ldg(as_ + (long)s0 * H + lane) + adv));
            w1 = __expf(leaky(__ldg(as_ + (long)s1 * H + lane) + adv));
            w2 = __expf(leaky(__ldg(as_ + (long)s2 * H + lane) + adv));
            w3 = __expf(leaky(__ldg(as_ + (long)s3 * H + lane) + adv));
            denom += (w0 + w1) + (w2 + w3);
        }
        const float* h0 = h + (long)s0 * D;
        const float* h1 = h + (long)s1 * D;
        const float* h2 = h + (long)s2 * D;
        const float* h3 = h + (long)s3 * D;
        #pragma unroll
        for (int i = 0; i < PER2; i++) {
            int k2 = 2 * lane + 64 * i;
            int sl = k2 / C;
            float wa = __shfl_sync(FULL, w0, sl);
            float wb = __shfl_sync(FULL, w1, sl);
            float wc = __shfl_sync(FULL, w2, sl);
            float wd = __shfl_sync(FULL, w3, sl);
            float2 v0 = *(const float2*)&h0[k2];
            float2 v1 = *(const float2*)&h1[k2];
            float2 v2 = *(const float2*)&h2[k2];
            float2 v3 = *(const float2*)&h3[k2];
            acc[i].x += wa * v0.x + wb * v1.x + wc * v2.x + wd * v3.x;
            acc[i].y += wa * v0.y + wb * v1.y + wc * v2.y + wd * v3.y;
        }
    }
    for (; j < r1; j++) {
        int s0 = g_col[j];
        float w0 = 0.f;
        if (lane < H) {
            w0 = __expf(leaky(__ldg(as_ + (long)s0 * H + lane) + adv));
            denom += w0;
        }
        const float* h0 = h + (long)s0 * D;
        #pragma unroll
        for (int i = 0; i < PER2; i++) {
            int k2 = 2 * lane + 64 * i;
            float wa = __shfl_sync(FULL, w0, k2 / C);
            float2 v0 = *(const float2*)&h0[k2];
            acc[i].x += wa * v0.x;
            acc[i].y += wa * v0.y;
        }
    }

    float rden = __frcp_rn(denom);
    #pragma unroll
    for (int i = 0; i < PER2; i++) {
        int k2 = 2 * lane + 64 * i;
        float rk = __shfl_sync(FULL, rden, k2 / C);
        float2 bv = *(const float2*)&bias[k2];
        float vx = acc[i].x * rk + bv.x;
        float vy = acc[i].y * rk + bv.y;
        vx = vx > 0.f ? vx : __expf(vx) - 1.f;
        vy = vy > 0.f ? vy : __expf(vy) - 1.f;
        *(float2*)&out[(long)node * D + k2] = make_float2(vx, vy);
    }
}

// ---------------- pair scoring head ----------------
__global__ void k_pair(const float* __restrict__ x, const int* __restrict__ n1,
                       const int* __restrict__ n2, const float* __restrict__ linW,
                       const float* __restrict__ linb, float* __restrict__ y) {
    int warp = (blockIdx.x * blockDim.x + threadIdx.x) >> 5;
    int lane = threadIdx.x & 31;
    if (warp >= PAIRS) return;
    int a = n1[warp], b = n2[warp];
    float p0 = 0.f, p1 = 0.f;
    #pragma unroll
    for (int i = 0; i < 4; i++) {
        int k = lane + 32 * i;
        float xv = (k < D2) ? x[(long)a * D2 + k] : x[(long)b * D2 + (k - D2)];
        p0 += xv * linW[k * 2 + 0];
        p1 += xv * linW[k * 2 + 1];
    }
    #pragma unroll
    for (int off = 16; off; off >>= 1) {
        p0 += __shfl_xor_sync(FULL, p0, off);
        p1 += __shfl_xor_sync(FULL, p1, off);
    }
    if (lane == 0) {
        float z0 = p0 + linb[0], z1 = p1 + linb[1];
        y[warp * 2 + 0] = 1.f / (1.f + __expf(-z0));
        y[warp * 2 + 1] = 1.f / (1.f + __expf(-z1));
    }
}

// ---------------- launcher with fork/join + agg1/GEMM2 pipelining ----------
extern "C" void kernel_launch(void* const* d_in, const int* in_sizes, int n_in,
                              void* d_out, int out_size) {
    const float* features = (const float*)d_in[0];
    const int*   edge_index = (const int*)d_in[1];
    const int*   n1 = (const int*)d_in[2];
    const int*   n2 = (const int*)d_in[3];
    const float* W1 = (const float*)d_in[4];
    const float* attS1 = (const float*)d_in[5];
    const float* attD1 = (const float*)d_in[6];
    const float* b1 = (const float*)d_in[7];
    const float* W2 = (const float*)d_in[8];
    const float* attS2 = (const float*)d_in[9];
    const float* attD2 = (const float*)d_in[10];
    const float* b2 = (const float*)d_in[11];
    const float* linW = (const float*)d_in[12];
    const float* linb = (const float*)d_in[13];

    float* out  = (float*)d_out;
    float* y    = out;               // y_pred: [PAIRS, 2]
    float* xout = out + PAIRS * 2;   // x:      [NN, D2]

    int E = in_sizes[1] / 2;
    int ETOT = E + NN;

    float *p_h1, *p_x1, *p_h2, *p_as1, *p_ad1, *p_as2, *p_ad2;
    cudaGetSymbolAddress((void**)&p_h1, g_h1);
    cudaGetSymbolAddress((void**)&p_x1, g_x1);
    cudaGetSymbolAddress((void**)&p_h2, g_h2);
    cudaGetSymbolAddress((void**)&p_as1, g_as1);
    cudaGetSymbolAddress((void**)&p_ad1, g_ad1);
    cudaGetSymbolAddress((void**)&p_as2, g_as2);
    cudaGetSymbolAddress((void**)&p_ad2, g_ad2);

    static cudaStream_t s2 = nullptr;
    static cudaEvent_t evFork = nullptr, evJoin = nullptr, evA = nullptr, evG = nullptr;
    if (!s2) {
        cudaStreamCreateWithFlags(&s2, cudaStreamNonBlocking);
        cudaEventCreateWithFlags(&evFork, cudaEventDisableTiming);
        cudaEventCreateWithFlags(&evJoin, cudaEventDisableTiming);
        cudaEventCreateWithFlags(&evA, cudaEventDisableTiming);
        cudaEventCreateWithFlags(&evG, cudaEventDisableTiming);
    }

    // fork: CSR build on s2 overlaps GEMM1 + attn1 on main stream
    cudaEventRecord(evFork, 0);
    cudaStreamWaitEvent(s2, evFork, 0);

    k_init_deg<<<(NN + 255) / 256, 256, 0, s2>>>();
    k_count<<<(ETOT + 255) / 256, 256, 0, s2>>>(edge_index, E, ETOT);
    k_scan<<<1, 1024, 0, s2>>>();
    k_scatter<<<(ETOT + 255) / 256, 256, 0, s2>>>(edge_index, E, ETOT);
    cudaEventRecord(evJoin, s2);

    {
        dim3 grid(D1 / 64, (NN + 127) / 128);
        k_gemm_tc<128, 64, 16><<<grid, 256>>>(features, W1, p_h1, NN, FEA, D1);
    }
    k_attn<H1, C1><<<(NN * H1 + 255) / 256, 256>>>(p_h1, attS1, attD1, p_as1, p_ad1);

    cudaStreamWaitEvent(0, evJoin, 0);

    // agg1 lo half, then pipeline: GEMM2-lo on s2 overlaps agg1 hi half
    k_agg<H1, C1><<<(NHALF * 32 + 255) / 256, 256>>>(p_h1, p_as1, p_ad1, b1, p_x1, 0, NHALF);
    cudaEventRecord(evA, 0);
    cudaStreamWaitEvent(s2, evA, 0);
    {
        dim3 grid(D2 / 64, NHALF / 128);
        k_gemm_tc<128, 64, 16><<<grid, 256, 0, s2>>>(p_x1, W2, p_h2, NHALF, D1, D2);
    }
    cudaEventRecord(evG, s2);

    k_agg<H1, C1><<<((NN - NHALF) * 32 + 255) / 256, 256>>>(p_h1, p_as1, p_ad1, b1, p_x1, NHALF, NN - NHALF);
    {
        dim3 grid(D2 / 64, (NN - NHALF + 127) / 128);
        k_gemm_tc<128, 64, 16><<<grid, 256>>>(p_x1 + (long)NHALF * D1, W2,
                                              p_h2 + (long)NHALF * D2, NN - NHALF, D1, D2);
    }
    cudaStreamWaitEvent(0, evG, 0);

    k_attn<H2, C2><<<(NN * H2 + 255) / 256, 256>>>(p_h2, attS2, attD2, p_as2, p_ad2);
    k_agg<H2, C2><<<(NN * 32 + 255) / 256, 256>>>(p_h2, p_as2, p_ad2, b2, xout, 0, NN);

    // Pair head
    k_pair<<<(PAIRS * 32 + 255) / 256, 256>>>(xout, n1, n2, linW, linb, y);
}

// round 8
// speedup vs baseline: 1.3364x; 1.1164x over previous
#include <cuda_runtime.h>
#include <cuda_fp16.h>
#include <cstdint>

#define FULL 0xffffffffu

constexpr int NN   = 50000;
constexpr int FEA  = 213;
constexpr int H1   = 12, C1 = 16, D1 = 192;
constexpr int H2   = 8,  C2 = 8,  D2 = 64;
constexpr int PAIRS = 16384;
constexpr int EMAX = 800000;
constexpr int ETOTMAX = EMAX + NN;
constexpr int NHALF = 25088;   // node split for agg1/GEMM2 pipelining (mult of 128)

// ---------------- device scratch (static, no runtime alloc) ----------------
__device__ float g_h1[NN * D1];
__device__ float g_x1[NN * D1];
__device__ float g_h2[NN * D2];
__device__ float g_as1[NN * H1];
__device__ float g_ad1[NN * H1];
__device__ float g_as2[NN * H2];
__device__ float g_ad2[NN * H2];
__device__ int   g_deg[NN];
__device__ int   g_cursor[NN];
__device__ int   g_rowptr[NN + 1];
__device__ int   g_col[ETOTMAX];

__device__ __forceinline__ float leaky(float x) { return x > 0.f ? x : 0.2f * x; }

// ---------------- CSR build ----------------
__global__ void k_init_deg() {
    int i = blockIdx.x * blockDim.x + threadIdx.x;
    if (i < NN) { g_deg[i] = 0; g_cursor[i] = 0; }
}

__global__ void k_count(const int* __restrict__ ei, int E, int ETOT) {
    int i = blockIdx.x * blockDim.x + threadIdx.x;
    if (i >= ETOT) return;
    int dst = (i < E) ? ei[E + i] : (i - E);
    atomicAdd(&g_deg[dst], 1);
}

__global__ void k_scan() {  // single block, 1024 threads
    __shared__ int s[1024];
    int t = threadIdx.x;
    const int chunk = (NN + 1023) / 1024;
    int start = t * chunk;
    int end = start + chunk; if (end > NN) end = NN; if (start > NN) start = NN;
    int sum = 0;
    for (int i = start; i < end; i++) sum += g_deg[i];
    s[t] = sum;
    __syncthreads();
    for (int off = 1; off < 1024; off <<= 1) {
        int v = 0;
        if (t >= off) v = s[t - off];
        __syncthreads();
        s[t] += v;
        __syncthreads();
    }
    int run = s[t] - sum;  // exclusive prefix
    for (int i = start; i < end; i++) { g_rowptr[i] = run; run += g_deg[i]; }
    if (t == 1023) g_rowptr[NN] = s[1023];
}

__global__ void k_scatter(const int* __restrict__ ei, int E, int ETOT) {
    int i = blockIdx.x * blockDim.x + threadIdx.x;
    if (i >= ETOT) return;
    int src, dst;
    if (i < E) { src = ei[i]; dst = ei[E + i]; }
    else       { src = dst = i - E; }
    int pos = atomicAdd(&g_cursor[dst], 1);
    g_col[g_rowptr[dst] + pos] = src;
}

// ------------- fp16-split (Markidis) tensor-core GEMM, m16n8k16 -------------
// x = big_h + sml_h; D += Ab*Bb + As*Bb + Ab*Bs (sml*sml dropped, ~2^-22 resid)
__device__ __forceinline__ void split_pair(float x0, float x1,
                                           uint32_t& bg, uint32_t& sm) {
    __half2 b = __floats2half2_rn(x0, x1);
    float2 bf = __half22float2(b);
    __half2 s = __floats2half2_rn(x0 - bf.x, x1 - bf.y);
    bg = *reinterpret_cast<uint32_t*>(&b);
    sm = *reinterpret_cast<uint32_t*>(&s);
}
__device__ __forceinline__ void mma_f16(float* c, const uint32_t* a, const uint32_t* b) {
    asm volatile(
        "mma.sync.aligned.m16n8k16.row.col.f32.f16.f16.f32 "
        "{%0,%1,%2,%3}, {%4,%5,%6,%7}, {%8,%9}, {%0,%1,%2,%3};"
        : "+f"(c[0]), "+f"(c[1]), "+f"(c[2]), "+f"(c[3])
        : "r"(a[0]), "r"(a[1]), "r"(a[2]), "r"(a[3]), "r"(b[0]), "r"(b[1]));
}

// C[M,Nc] = A[M,K] @ B[K,Nc]. 256 threads = 8 warps (4 along M x 2 along N).
// Block tile 128x64, BK=16 (one k16 MMA chunk per tile). Smem holds big/small
// half2 k-pair planes, stride +8 -> conflict-free LDS.32 fragment loads.
// Double-buffered; split conversion happens in the (overlapped) load phase.
template <int BM, int BN, int BK>
__global__ void __launch_bounds__(256)
k_gemm_hs(const float* __restrict__ A, const float* __restrict__ B,
          float* __restrict__ Cm, int M, int K, int Nc) {
    constexpr int KP  = BK / 2;        // 8 k-pairs
    constexpr int AST = BM + 8;        // plane strides (uint32 units)
    constexpr int BST = BN + 8;
    __shared__ uint32_t AsB[2][KP][AST], AsS[2][KP][AST];
    __shared__ uint32_t BsB[2][KP][BST], BsS[2][KP][BST];
    constexpr int ALD = BM * KP / 256;   // 4 pairs per thread
    constexpr int BLD = BN * KP / 256;   // 2 pairs per thread
    int t = threadIdx.x;
    int lane = t & 31, wid = t >> 5;
    int wm = wid & 3, wn = wid >> 2;
    int cq = lane & 3, gq = lane >> 2;
    int bm = blockIdx.y * BM, bn = blockIdx.x * BN;
    float acc[2][4][4] = {};
    uint32_t rabg[ALD], rasm[ALD], rbbg[BLD], rbsm[BLD];

    // prologue: tile 0
    #pragma unroll
    for (int u = 0; u < ALD; u++) {
        int i = t + 256 * u;
        int r = i >> 3, kp = i & 7;    // KP==8
        int row = bm + r;
        int k0 = 2 * kp;
        float x0 = (row < M && k0     < K) ? A[(long)row * K + k0]     : 0.f;
        float x1 = (row < M && k0 + 1 < K) ? A[(long)row * K + k0 + 1] : 0.f;
        uint32_t bg, sm;
        split_pair(x0, x1, bg, sm);
        AsB[0][kp][r] = bg; AsS[0][kp][r] = sm;
    }
    #pragma unroll
    for (int u = 0; u < BLD; u++) {
        int i = t + 256 * u;
        int col = i % BN, kp = i / BN;
        int k0 = 2 * kp;
        float x0 = (k0     < K) ? B[(long)k0       * Nc + bn + col] : 0.f;
        float x1 = (k0 + 1 < K) ? B[(long)(k0 + 1) * Nc + bn + col] : 0.f;
        uint32_t bg, sm;
        split_pair(x0, x1, bg, sm);
        BsB[0][kp][col] = bg; BsS[0][kp][col] = sm;
    }
    __syncthreads();

    int nTiles = (K + BK - 1) / BK;
    for (int tile = 0; tile < nTiles; tile++) {
        int buf = tile & 1;
        int k0n = (tile + 1) * BK;
        if (tile + 1 < nTiles) {
            #pragma unroll
            for (int u = 0; u < ALD; u++) {
                int i = t + 256 * u;
                int r = i >> 3, kp = i & 7;
                int row = bm + r;
                int k0 = k0n + 2 * kp;
                float x0 = (row < M && k0     < K) ? A[(long)row * K + k0]     : 0.f;
                float x1 = (row < M && k0 + 1 < K) ? A[(long)row * K + k0 + 1] : 0.f;
                split_pair(x0, x1, rabg[u], rasm[u]);
            }
            #pragma unroll
            for (int u = 0; u < BLD; u++) {
                int i = t + 256 * u;
                int col = i % BN, kp = i / BN;
                int k0 = k0n + 2 * kp;
                float x0 = (k0     < K) ? B[(long)k0       * Nc + bn + col] : 0.f;
                float x1 = (k0 + 1 < K) ? B[(long)(k0 + 1) * Nc + bn + col] : 0.f;
                split_pair(x0, x1, rbbg[u], rbsm[u]);
            }
        }
        // compute one k16 chunk: pure LDS.32 + HMMA
        {
            uint32_t ab[2][4], as_[2][4];
            #pragma unroll
            for (int mt = 0; mt < 2; mt++) {
                int row = wm * 32 + mt * 16 + gq;
                ab[mt][0]  = AsB[buf][cq][row];     ab[mt][1]  = AsB[buf][cq][row + 8];
                ab[mt][2]  = AsB[buf][cq + 4][row]; ab[mt][3]  = AsB[buf][cq + 4][row + 8];
                as_[mt][0] = AsS[buf][cq][row];     as_[mt][1] = AsS[buf][cq][row + 8];
                as_[mt][2] = AsS[buf][cq + 4][row]; as_[mt][3] = AsS[buf][cq + 4][row + 8];
            }
            uint32_t bb[4][2], bs[4][2];
            #pragma unroll
            for (int nt = 0; nt < 4; nt++) {
                int col = wn * 32 + nt * 8 + gq;
                bb[nt][0] = BsB[buf][cq][col]; bb[nt][1] = BsB[buf][cq + 4][col];
                bs[nt][0] = BsS[buf][cq][col]; bs[nt][1] = BsS[buf][cq + 4][col];
            }
            #pragma unroll
            for (int mt = 0; mt < 2; mt++)
                #pragma unroll
                for (int nt = 0; nt < 4; nt++) {
                    mma_f16(acc[mt][nt], as_[mt], bb[nt]);
                    mma_f16(acc[mt][nt], ab[mt],  bs[nt]);
                    mma_f16(acc[mt][nt], ab[mt],  bb[nt]);
                }
        }
        if (tile + 1 < nTiles) {
            __syncthreads();
            int nb = buf ^ 1;
            #pragma unroll
            for (int u = 0; u < ALD; u++) {
                int i = t + 256 * u;
                int r = i >> 3, kp = i & 7;
                AsB[nb][kp][r] = rabg[u]; AsS[nb][kp][r] = rasm[u];
            }
            #pragma unroll
            for (int u = 0; u < BLD; u++) {
                int i = t + 256 * u;
                int col = i % BN, kp = i / BN;
                BsB[nb][kp][col] = rbbg[u]; BsS[nb][kp][col] = rbsm[u];
            }
            __syncthreads();
        }
    }
    // epilogue: C fragment (gid, 2c) / (gid+8, 2c) pairs
    #pragma unroll
    for (int mt = 0; mt < 2; mt++) {
        int row0 = bm + wm * 32 + mt * 16 + gq;
        #pragma unroll
        for (int nt = 0; nt < 4; nt++) {
            int col = bn + wn * 32 + nt * 8 + 2 * cq;
            if (row0 < M)
                *(float2*)&Cm[(long)row0 * Nc + col] =
                    make_float2(acc[mt][nt][0], acc[mt][nt][1]);
            if (row0 + 8 < M)
                *(float2*)&Cm[(long)(row0 + 8) * Nc + col] =
                    make_float2(acc[mt][nt][2], acc[mt][nt][3]);
        }
    }
}

// ---------------- attention scores a_src, a_dst (float4 loads) ----------------
template <int H, int C>
__global__ void k_attn(const float* __restrict__ h, const float* __restrict__ aS,
                       const float* __restrict__ aD, float* __restrict__ s_,
                       float* __restrict__ d_) {
    int i = blockIdx.x * blockDim.x + threadIdx.x;
    if (i >= NN * H) return;
    int n = i / H, hh = i % H;
    const float4* hp = (const float4*)(h + (long)n * H * C + hh * C);
    const float4* sp = (const float4*)(aS + hh * C);
    const float4* dp = (const float4*)(aD + hh * C);
    float s = 0.f, d = 0.f;
    #pragma unroll
    for (int c = 0; c < C / 4; c++) {
        float4 v = hp[c], a = sp[c], b = dp[c];
        s += v.x * a.x + v.y * a.y + v.z * a.z + v.w * a.w;
        d += v.x * b.x + v.y * b.y + v.z * b.z + v.w * b.w;
    }
    s_[i] = s; d_[i] = d;
}

// ---------------- warp-per-node segment-softmax aggregation (float2) --------
// Processes nodes [n0, n0+cnt). Max-free softmax, fused single pass, x4 unroll.
template <int H, int C>
__global__ void k_agg(const float* __restrict__ h, const float* __restrict__ as_,
                      const float* __restrict__ ad_, const float* __restrict__ bias,
                      float* __restrict__ out, int n0, int cnt) {
    constexpr int D = H * C;
    constexpr int PER2 = D / 64;
    int warp = (blockIdx.x * blockDim.x + threadIdx.x) >> 5;
    int lane = threadIdx.x & 31;
    if (warp >= cnt) return;
    int node = n0 + warp;
    int r0 = g_rowptr[node];
    int r1 = g_rowptr[node + 1];

    float adv = (lane < H) ? ad_[node * H + lane] : 0.f;

    float2 acc[PER2];
    #pragma unroll
    for (int i = 0; i < PER2; i++) acc[i] = make_float2(0.f, 0.f);
    float denom = 0.f;
    int j = r0;
    for (; j + 3 < r1; j += 4) {
        int s0 = g_col[j], s1 = g_col[j + 1], s2 = g_col[j + 2], s3 = g_col[j + 3];
        float w0 = 0.f, w1 = 0.f, w2 = 0.f, w3 = 0.f;
        if (lane < H) {
            w0 = __expf(leaky(__ldg(as_ + (long)s0 * H + lane) + adv));
            w1 = __expf(leaky(__ldg(as_ + (long)s1 * H + lane) + adv));
            w2 = __expf(leaky(__ldg(as_ + (long)s2 * H + lane) + adv));
            w3 = __expf(leaky(__ldg(as_ + (long)s3 * H + lane) + adv));
            denom += (w0 + w1) + (w2 + w3);
        }
        const float* h0 = h + (long)s0 * D;
        const float* h1 = h + (long)s1 * D;
        const float* h2 = h + (long)s2 * D;
        const float* h3 = h + (long)s3 * D;
        #pragma unroll
        for (int i = 0; i < PER2; i++) {
            int k2 = 2 * lane + 64 * i;
            int sl = k2 / C;
            float wa = __shfl_sync(FULL, w0, sl);
            float wb = __shfl_sync(FULL, w1, sl);
            float wc = __shfl_sync(FULL, w2, sl);
            float wd = __shfl_sync(FULL, w3, sl);
            float2 v0 = *(const float2*)&h0[k2];
            float2 v1 = *(const float2*)&h1[k2];
            float2 v2 = *(const float2*)&h2[k2];
            float2 v3 = *(const float2*)&h3[k2];
            acc[i].x += wa * v0.x + wb * v1.x + wc * v2.x + wd * v3.x;
            acc[i].y += wa * v0.y + wb * v1.y + wc * v2.y + wd * v3.y;
        }
    }
    for (; j < r1; j++) {
        int s0 = g_col[j];
        float w0 = 0.f;
        if (lane < H) {
            w0 = __expf(leaky(__ldg(as_ + (long)s0 * H + lane) + adv));
            denom += w0;
        }
        const float* h0 = h + (long)s0 * D;
        #pragma unroll
        for (int i = 0; i < PER2; i++) {
            int k2 = 2 * lane + 64 * i;
            float wa = __shfl_sync(FULL, w0, k2 / C);
            float2 v0 = *(const float2*)&h0[k2];
            acc[i].x += wa * v0.x;
            acc[i].y += wa * v0.y;
        }
    }

    float rden = __frcp_rn(denom);
    #pragma unroll
    for (int i = 0; i < PER2; i++) {
        int k2 = 2 * lane + 64 * i;
        float rk = __shfl_sync(FULL, rden, k2 / C);
        float2 bv = *(const float2*)&bias[k2];
        float vx = acc[i].x * rk + bv.x;
        float vy = acc[i].y * rk + bv.y;
        vx = vx > 0.f ? vx : __expf(vx) - 1.f;
        vy = vy > 0.f ? vy : __expf(vy) - 1.f;
        *(float2*)&out[(long)node * D + k2] = make_float2(vx, vy);
    }
}

// ---------------- pair scoring head ----------------
__global__ void k_pair(const float* __restrict__ x, const int* __restrict__ n1,
                       const int* __restrict__ n2, const float* __restrict__ linW,
                       const float* __restrict__ linb, float* __restrict__ y) {
    int warp = (blockIdx.x * blockDim.x + threadIdx.x) >> 5;
    int lane = threadIdx.x & 31;
    if (warp >= PAIRS) return;
    int a = n1[warp], b = n2[warp];
    float p0 = 0.f, p1 = 0.f;
    #pragma unroll
    for (int i = 0; i < 4; i++) {
        int k = lane + 32 * i;
        float xv = (k < D2) ? x[(long)a * D2 + k] : x[(long)b * D2 + (k - D2)];
        p0 += xv * linW[k * 2 + 0];
        p1 += xv * linW[k * 2 + 1];
    }
    #pragma unroll
    for (int off = 16; off; off >>= 1) {
        p0 += __shfl_xor_sync(FULL, p0, off);
        p1 += __shfl_xor_sync(FULL, p1, off);
    }
    if (lane == 0) {
        float z0 = p0 + linb[0], z1 = p1 + linb[1];
        y[warp * 2 + 0] = 1.f / (1.f + __expf(-z0));
        y[warp * 2 + 1] = 1.f / (1.f + __expf(-z1));
    }
}

// ---------------- launcher with fork/join + agg1/GEMM2 pipelining ----------
extern "C" void kernel_launch(void* const* d_in, const int* in_sizes, int n_in,
                              void* d_out, int out_size) {
    const float* features = (const float*)d_in[0];
    const int*   edge_index = (const int*)d_in[1];
    const int*   n1 = (const int*)d_in[2];
    const int*   n2 = (const int*)d_in[3];
    const float* W1 = (const float*)d_in[4];
    const float* attS1 = (const float*)d_in[5];
    const float* attD1 = (const float*)d_in[6];
    const float* b1 = (const float*)d_in[7];
    const float* W2 = (const float*)d_in[8];
    const float* attS2 = (const float*)d_in[9];
    const float* attD2 = (const float*)d_in[10];
    const float* b2 = (const float*)d_in[11];
    const float* linW = (const float*)d_in[12];
    const float* linb = (const float*)d_in[13];

    float* out  = (float*)d_out;
    float* y    = out;               // y_pred: [PAIRS, 2]
    float* xout = out + PAIRS * 2;   // x:      [NN, D2]

    int E = in_sizes[1] / 2;
    int ETOT = E + NN;

    float *p_h1, *p_x1, *p_h2, *p_as1, *p_ad1, *p_as2, *p_ad2;
    cudaGetSymbolAddress((void**)&p_h1, g_h1);
    cudaGetSymbolAddress((void**)&p_x1, g_x1);
    cudaGetSymbolAddress((void**)&p_h2, g_h2);
    cudaGetSymbolAddress((void**)&p_as1, g_as1);
    cudaGetSymbolAddress((void**)&p_ad1, g_ad1);
    cudaGetSymbolAddress((void**)&p_as2, g_as2);
    cudaGetSymbolAddress((void**)&p_ad2, g_ad2);

    static cudaStream_t s2 = nullptr;
    static cudaEvent_t evFork = nullptr, evJoin = nullptr, evA = nullptr, evG = nullptr;
    if (!s2) {
        cudaStreamCreateWithFlags(&s2, cudaStreamNonBlocking);
        cudaEventCreateWithFlags(&evFork, cudaEventDisableTiming);
        cudaEventCreateWithFlags(&evJoin, cudaEventDisableTiming);
        cudaEventCreateWithFlags(&evA, cudaEventDisableTiming);
        cudaEventCreateWithFlags(&evG, cudaEventDisableTiming);
    }

    // fork: CSR build on s2 overlaps GEMM1 + attn1 on main stream
    cudaEventRecord(evFork, 0);
    cudaStreamWaitEvent(s2, evFork, 0);

    k_init_deg<<<(NN + 255) / 256, 256, 0, s2>>>();
    k_count<<<(ETOT + 255) / 256, 256, 0, s2>>>(edge_index, E, ETOT);
    k_scan<<<1, 1024, 0, s2>>>();
    k_scatter<<<(ETOT + 255) / 256, 256, 0, s2>>>(edge_index, E, ETOT);
    cudaEventRecord(evJoin, s2);

    {
        dim3 grid(D1 / 64, (NN + 127) / 128);
        k_gemm_hs<128, 64, 16><<<grid, 256>>>(features, W1, p_h1, NN, FEA, D1);
    }
    k_attn<H1, C1><<<(NN * H1 + 255) / 256, 256>>>(p_h1, attS1, attD1, p_as1, p_ad1);

    cudaStreamWaitEvent(0, evJoin, 0);

    // agg1 lo half, then pipeline: GEMM2-lo on s2 overlaps agg1 hi half
    k_agg<H1, C1><<<(NHALF * 32 + 255) / 256, 256>>>(p_h1, p_as1, p_ad1, b1, p_x1, 0, NHALF);
    cudaEventRecord(evA, 0);
    cudaStreamWaitEvent(s2, evA, 0);
    {
        dim3 grid(D2 / 64, NHALF / 128);
        k_gemm_hs<128, 64, 16><<<grid, 256, 0, s2>>>(p_x1, W2, p_h2, NHALF, D1, D2);
    }
    cudaEventRecord(evG, s2);

    k_agg<H1, C1><<<((NN - NHALF) * 32 + 255) / 256, 256>>>(p_h1, p_as1, p_ad1, b1, p_x1, NHALF, NN - NHALF);
    {
        dim3 grid(D2 / 64, (NN - NHALF + 127) / 128);
        k_gemm_hs<128, 64, 16><<<grid, 256>>>(p_x1 + (long)NHALF * D1, W2,
                                              p_h2 + (long)NHALF * D2, NN - NHALF, D1, D2);
    }
    cudaStreamWaitEvent(0, evG, 0);

    k_attn<H2, C2><<<(NN * H2 + 255) / 256, 256>>>(p_h2, attS2, attD2, p_as2, p_ad2);
    k_agg<H2, C2><<<(NN * 32 + 255) / 256, 256>>>(p_h2, p_as2, p_ad2, b2, xout, 0, NN);

    // Pair head
    k_pair<<<(PAIRS * 32 + 255) / 256, 256>>>(xout, n1, n2, linW, linb, y);
}

// round 9
// speedup vs baseline: 1.4075x; 1.0532x over previous
#include <cuda_runtime.h>
#include <cuda_fp16.h>
#include <cstdint>

#define FULL 0xffffffffu

constexpr int NN   = 50000;
constexpr int FEA  = 213;
constexpr int H1   = 12, C1 = 16, D1 = 192;
constexpr int H2   = 8,  C2 = 8,  D2 = 64;
constexpr int PAIRS = 16384;
constexpr int EMAX = 800000;
constexpr int ETOTMAX = EMAX + NN;
constexpr int NHALF = 25088;   // node split for agg1/GEMM2 pipelining (mult of 128)

// ---------------- device scratch (static, no runtime alloc) ----------------
__device__ __half g_h1[NN * D1];    // layer-1 features, fp16 (gather-bound)
__device__ float  g_x1[NN * D1];    // layer-1 output (post elu), fp32
__device__ __half g_h2[NN * D2];    // layer-2 features, fp16
__device__ float  g_as1[NN * H1];
__device__ float  g_ad1[NN * H1];
__device__ float  g_as2[NN * H2];
__device__ float  g_ad2[NN * H2];
__device__ int    g_deg[NN];
__device__ int    g_cursor[NN];
__device__ int    g_rowptr[NN + 1];
__device__ int    g_col[ETOTMAX];

__device__ __forceinline__ float leaky(float x) { return x > 0.f ? x : 0.2f * x; }

// ---------------- CSR build ----------------
__global__ void k_init_deg() {
    int i = blockIdx.x * blockDim.x + threadIdx.x;
    if (i < NN) { g_deg[i] = 0; g_cursor[i] = 0; }
}

__global__ void k_count(const int* __restrict__ ei, int E, int ETOT) {
    int i = blockIdx.x * blockDim.x + threadIdx.x;
    if (i >= ETOT) return;
    int dst = (i < E) ? ei[E + i] : (i - E);
    atomicAdd(&g_deg[dst], 1);
}

__global__ void k_scan() {  // single block, 1024 threads
    __shared__ int s[1024];
    int t = threadIdx.x;
    const int chunk = (NN + 1023) / 1024;
    int start = t * chunk;
    int end = start + chunk; if (end > NN) end = NN; if (start > NN) start = NN;
    int sum = 0;
    for (int i = start; i < end; i++) sum += g_deg[i];
    s[t] = sum;
    __syncthreads();
    for (int off = 1; off < 1024; off <<= 1) {
        int v = 0;
        if (t >= off) v = s[t - off];
        __syncthreads();
        s[t] += v;
        __syncthreads();
    }
    int run = s[t] - sum;  // exclusive prefix
    for (int i = start; i < end; i++) { g_rowptr[i] = run; run += g_deg[i]; }
    if (t == 1023) g_rowptr[NN] = s[1023];
}

__global__ void k_scatter(const int* __restrict__ ei, int E, int ETOT) {
    int i = blockIdx.x * blockDim.x + threadIdx.x;
    if (i >= ETOT) return;
    int src, dst;
    if (i < E) { src = ei[i]; dst = ei[E + i]; }
    else       { src = dst = i - E; }
    int pos = atomicAdd(&g_cursor[dst], 1);
    g_col[g_rowptr[dst] + pos] = src;
}

// ------------- fp16-split (Markidis) tensor-core GEMM, m16n8k16 -------------
// x = big_h + sml_h; D += Ab*Bb + As*Bb + Ab*Bs.  Output written as __half2.
__device__ __forceinline__ void split_pair(float x0, float x1,
                                           uint32_t& bg, uint32_t& sm) {
    __half2 b = __floats2half2_rn(x0, x1);
    float2 bf = __half22float2(b);
    __half2 s = __floats2half2_rn(x0 - bf.x, x1 - bf.y);
    bg = *reinterpret_cast<uint32_t*>(&b);
    sm = *reinterpret_cast<uint32_t*>(&s);
}
__device__ __forceinline__ void mma_f16(float* c, const uint32_t* a, const uint32_t* b) {
    asm volatile(
        "mma.sync.aligned.m16n8k16.row.col.f32.f16.f16.f32 "
        "{%0,%1,%2,%3}, {%4,%5,%6,%7}, {%8,%9}, {%0,%1,%2,%3};"
        : "+f"(c[0]), "+f"(c[1]), "+f"(c[2]), "+f"(c[3])
        : "r"(a[0]), "r"(a[1]), "r"(a[2]), "r"(a[3]), "r"(b[0]), "r"(b[1]));
}

// C_h[M,Nc] (__half) = A[M,K] @ B[K,Nc]. 256 threads = 8 warps (4 M x 2 N).
// Block tile 128x64, BK=16. Big/small half2 k-pair planes in smem,
// stride +8 -> conflict-free LDS.32. Double-buffered.
template <int BM, int BN, int BK>
__global__ void __launch_bounds__(256)
k_gemm_hs(const float* __restrict__ A, const float* __restrict__ B,
          __half* __restrict__ Cm, int M, int K, int Nc) {
    constexpr int KP  = BK / 2;
    constexpr int AST = BM + 8;
    constexpr int BST = BN + 8;
    __shared__ uint32_t AsB[2][KP][AST], AsS[2][KP][AST];
    __shared__ uint32_t BsB[2][KP][BST], BsS[2][KP][BST];
    constexpr int ALD = BM * KP / 256;   // 4
    constexpr int BLD = BN * KP / 256;   // 2
    int t = threadIdx.x;
    int lane = t & 31, wid = t >> 5;
    int wm = wid & 3, wn = wid >> 2;
    int cq = lane & 3, gq = lane >> 2;
    int bm = blockIdx.y * BM, bn = blockIdx.x * BN;
    float acc[2][4][4] = {};
    uint32_t rabg[ALD], rasm[ALD], rbbg[BLD], rbsm[BLD];

    #pragma unroll
    for (int u = 0; u < ALD; u++) {
        int i = t + 256 * u;
        int r = i >> 3, kp = i & 7;
        int row = bm + r;
        int k0 = 2 * kp;
        float x0 = (row < M && k0     < K) ? A[(long)row * K + k0]     : 0.f;
        float x1 = (row < M && k0 + 1 < K) ? A[(long)row * K + k0 + 1] : 0.f;
        uint32_t bg, sm;
        split_pair(x0, x1, bg, sm);
        AsB[0][kp][r] = bg; AsS[0][kp][r] = sm;
    }
    #pragma unroll
    for (int u = 0; u < BLD; u++) {
        int i = t + 256 * u;
        int col = i % BN, kp = i / BN;
        int k0 = 2 * kp;
        float x0 = (k0     < K) ? B[(long)k0       * Nc + bn + col] : 0.f;
        float x1 = (k0 + 1 < K) ? B[(long)(k0 + 1) * Nc + bn + col] : 0.f;
        uint32_t bg, sm;
        split_pair(x0, x1, bg, sm);
        BsB[0][kp][col] = bg; BsS[0][kp][col] = sm;
    }
    __syncthreads();

    int nTiles = (K + BK - 1) / BK;
    for (int tile = 0; tile < nTiles; tile++) {
        int buf = tile & 1;
        int k0n = (tile + 1) * BK;
        if (tile + 1 < nTiles) {
            #pragma unroll
            for (int u = 0; u < ALD; u++) {
                int i = t + 256 * u;
                int r = i >> 3, kp = i & 7;
                int row = bm + r;
                int k0 = k0n + 2 * kp;
                float x0 = (row < M && k0     < K) ? A[(long)row * K + k0]     : 0.f;
                float x1 = (row < M && k0 + 1 < K) ? A[(long)row * K + k0 + 1] : 0.f;
                split_pair(x0, x1, rabg[u], rasm[u]);
            }
            #pragma unroll
            for (int u = 0; u < BLD; u++) {
                int i = t + 256 * u;
                int col = i % BN, kp = i / BN;
                int k0 = k0n + 2 * kp;
                float x0 = (k0     < K) ? B[(long)k0       * Nc + bn + col] : 0.f;
                float x1 = (k0 + 1 < K) ? B[(long)(k0 + 1) * Nc + bn + col] : 0.f;
                split_pair(x0, x1, rbbg[u], rbsm[u]);
            }
        }
        {
            uint32_t ab[2][4], as_[2][4];
            #pragma unroll
            for (int mt = 0; mt < 2; mt++) {
                int row = wm * 32 + mt * 16 + gq;
                ab[mt][0]  = AsB[buf][cq][row];     ab[mt][1]  = AsB[buf][cq][row + 8];
                ab[mt][2]  = AsB[buf][cq + 4][row]; ab[mt][3]  = AsB[buf][cq + 4][row + 8];
                as_[mt][0] = AsS[buf][cq][row];     as_[mt][1] = AsS[buf][cq][row + 8];
                as_[mt][2] = AsS[buf][cq + 4][row]; as_[mt][3] = AsS[buf][cq + 4][row + 8];
            }
            uint32_t bb[4][2], bs[4][2];
            #pragma unroll
            for (int nt = 0; nt < 4; nt++) {
                int col = wn * 32 + nt * 8 + gq;
                bb[nt][0] = BsB[buf][cq][col]; bb[nt][1] = BsB[buf][cq + 4][col];
                bs[nt][0] = BsS[buf][cq][col]; bs[nt][1] = BsS[buf][cq + 4][col];
            }
            #pragma unroll
            for (int mt = 0; mt < 2; mt++)
                #pragma unroll
                for (int nt = 0; nt < 4; nt++) {
                    mma_f16(acc[mt][nt], as_[mt], bb[nt]);
                    mma_f16(acc[mt][nt], ab[mt],  bs[nt]);
                    mma_f16(acc[mt][nt], ab[mt],  bb[nt]);
                }
        }
        if (tile + 1 < nTiles) {
            __syncthreads();
            int nb = buf ^ 1;
            #pragma unroll
            for (int u = 0; u < ALD; u++) {
                int i = t + 256 * u;
                int r = i >> 3, kp = i & 7;
                AsB[nb][kp][r] = rabg[u]; AsS[nb][kp][r] = rasm[u];
            }
            #pragma unroll
            for (int u = 0; u < BLD; u++) {
                int i = t + 256 * u;
                int col = i % BN, kp = i / BN;
                BsB[nb][kp][col] = rbbg[u]; BsS[nb][kp][col] = rbsm[u];
            }
            __syncthreads();
        }
    }
    // epilogue: write half2 pairs
    #pragma unroll
    for (int mt = 0; mt < 2; mt++) {
        int row0 = bm + wm * 32 + mt * 16 + gq;
        #pragma unroll
        for (int nt = 0; nt < 4; nt++) {
            int col = bn + wn * 32 + nt * 8 + 2 * cq;
            if (row0 < M)
                *(__half2*)&Cm[(long)row0 * Nc + col] =
                    __floats2half2_rn(acc[mt][nt][0], acc[mt][nt][1]);
            if (row0 + 8 < M)
                *(__half2*)&Cm[(long)(row0 + 8) * Nc + col] =
                    __floats2half2_rn(acc[mt][nt][2], acc[mt][nt][3]);
        }
    }
}

// ---------------- attention scores a_src, a_dst (half2 features) ------------
template <int H, int C>
__global__ void k_attn(const __half* __restrict__ h, const float* __restrict__ aS,
                       const float* __restrict__ aD, float* __restrict__ s_,
                       float* __restrict__ d_) {
    int i = blockIdx.x * blockDim.x + threadIdx.x;
    if (i >= NN * H) return;
    int n = i / H, hh = i % H;
    const __half2* hp = (const __half2*)(h + (long)n * H * C + hh * C);
    float s = 0.f, d = 0.f;
    #pragma unroll
    for (int c = 0; c < C / 2; c++) {
        float2 v = __half22float2(hp[c]);
        s += v.x * aS[hh * C + 2 * c] + v.y * aS[hh * C + 2 * c + 1];
        d += v.x * aD[hh * C + 2 * c] + v.y * aD[hh * C + 2 * c + 1];
    }
    s_[i] = s; d_[i] = d;
}

// ---------------- warp-per-node segment-softmax aggregation (half2 gather) --
// Processes nodes [n0, n0+cnt). Max-free softmax, fused single pass, x4 unroll.
// h is fp16; accumulation fp32.
template <int H, int C>
__global__ void k_agg(const __half* __restrict__ h, const float* __restrict__ as_,
                      const float* __restrict__ ad_, const float* __restrict__ bias,
                      float* __restrict__ out, int n0, int cnt) {
    constexpr int D = H * C;
    constexpr int PER2 = D / 64;
    int warp = (blockIdx.x * blockDim.x + threadIdx.x) >> 5;
    int lane = threadIdx.x & 31;
    if (warp >= cnt) return;
    int node = n0 + warp;
    int r0 = g_rowptr[node];
    int r1 = g_rowptr[node + 1];

    float adv = (lane < H) ? ad_[node * H + lane] : 0.f;

    float2 acc[PER2];
    #pragma unroll
    for (int i = 0; i < PER2; i++) acc[i] = make_float2(0.f, 0.f);
    float denom = 0.f;
    int j = r0;
    for (; j + 3 < r1; j += 4) {
        int s0 = g_col[j], s1 = g_col[j + 1], s2 = g_col[j + 2], s3 = g_col[j + 3];
        float w0 = 0.f, w1 = 0.f, w2 = 0.f, w3 = 0.f;
        if (lane < H) {
            w0 = __expf(leaky(__ldg(as_ + (long)s0 * H + lane) + adv));
            w1 = __expf(leaky(__ldg(as_ + (long)s1 * H + lane) + adv));
            w2 = __expf(leaky(__ldg(as_ + (long)s2 * H + lane) + adv));
            w3 = __expf(leaky(__ldg(as_ + (long)s3 * H + lane) + adv));
            denom += (w0 + w1) + (w2 + w3);
        }
        const __half2* h0 = (const __half2*)(h + (long)s0 * D);
        const __half2* h1 = (const __half2*)(h + (long)s1 * D);
        const __half2* h2 = (const __half2*)(h + (long)s2 * D);
        const __half2* h3 = (const __half2*)(h + (long)s3 * D);
        #pragma unroll
        for (int i = 0; i < PER2; i++) {
            int k2 = 2 * lane + 64 * i;       // element index (even)
            int p  = lane + 32 * i;           // half2 index
            int sl = k2 / C;
            float wa = __shfl_sync(FULL, w0, sl);
            float wb = __shfl_sync(FULL, w1, sl);
            float wc = __shfl_sync(FULL, w2, sl);
            float wd = __shfl_sync(FULL, w3, sl);
            float2 v0 = __half22float2(h0[p]);
            float2 v1 = __half22float2(h1[p]);
            float2 v2 = __half22float2(h2[p]);
            float2 v3 = __half22float2(h3[p]);
            acc[i].x += wa * v0.x + wb * v1.x + wc * v2.x + wd * v3.x;
            acc[i].y += wa * v0.y + wb * v1.y + wc * v2.y + wd * v3.y;
        }
    }
    for (; j < r1; j++) {
        int s0 = g_col[j];
        float w0 = 0.f;
        if (lane < H) {
            w0 = __expf(leaky(__ldg(as_ + (long)s0 * H + lane) + adv));
            denom += w0;
        }
        const __half2* h0 = (const __half2*)(h + (long)s0 * D);
        #pragma unroll
        for (int i = 0; i < PER2; i++) {
            int k2 = 2 * lane + 64 * i;
            int p  = lane + 32 * i;
            float wa = __shfl_sync(FULL, w0, k2 / C);
            float2 v0 = __half22float2(h0[p]);
            acc[i].x += wa * v0.x;
            acc[i].y += wa * v0.y;
        }
    }

    float rden = __frcp_rn(denom);
    #pragma unroll
    for (int i = 0; i < PER2; i++) {
        int k2 = 2 * lane + 64 * i;
        float rk = __shfl_sync(FULL, rden, k2 / C);
        float2 bv = *(const float2*)&bias[k2];
        float vx = acc[i].x * rk + bv.x;
        float vy = acc[i].y * rk + bv.y;
        vx = vx > 0.f ? vx : __expf(vx) - 1.f;
        vy = vy > 0.f ? vy : __expf(vy) - 1.f;
        *(float2*)&out[(long)node * D + k2] = make_float2(vx, vy);
    }
}

// ---------------- pair scoring head ----------------
__global__ void k_pair(const float* __restrict__ x, const int* __restrict__ n1,
                       const int* __restrict__ n2, const float* __restrict__ linW,
                       const float* __restrict__ linb, float* __restrict__ y) {
    int warp = (blockIdx.x * blockDim.x + threadIdx.x) >> 5;
    int lane = threadIdx.x & 31;
    if (warp >= PAIRS) return;
    int a = n1[warp], b = n2[warp];
    float p0 = 0.f, p1 = 0.f;
    #pragma unroll
    for (int i = 0; i < 4; i++) {
        int k = lane + 32 * i;
        float xv = (k < D2) ? x[(long)a * D2 + k] : x[(long)b * D2 + (k - D2)];
        p0 += xv * linW[k * 2 + 0];
        p1 += xv * linW[k * 2 + 1];
    }
    #pragma unroll
    for (int off = 16; off; off >>= 1) {
        p0 += __shfl_xor_sync(FULL, p0, off);
        p1 += __shfl_xor_sync(FULL, p1, off);
    }
    if (lane == 0) {
        float z0 = p0 + linb[0], z1 = p1 + linb[1];
        y[warp * 2 + 0] = 1.f / (1.f + __expf(-z0));
        y[warp * 2 + 1] = 1.f / (1.f + __expf(-z1));
    }
}

// ---------------- launcher with fork/join + agg1/GEMM2 pipelining ----------
extern "C" void kernel_launch(void* const* d_in, const int* in_sizes, int n_in,
                              void* d_out, int out_size) {
    const float* features = (const float*)d_in[0];
    const int*   edge_index = (const int*)d_in[1];
    const int*   n1 = (const int*)d_in[2];
    const int*   n2 = (const int*)d_in[3];
    const float* W1 = (const float*)d_in[4];
    const float* attS1 = (const float*)d_in[5];
    const float* attD1 = (const float*)d_in[6];
    const float* b1 = (const float*)d_in[7];
    const float* W2 = (const float*)d_in[8];
    const float* attS2 = (const float*)d_in[9];
    const float* attD2 = (const float*)d_in[10];
    const float* b2 = (const float*)d_in[11];
    const float* linW = (const float*)d_in[12];
    const float* linb = (const float*)d_in[13];

    float* out  = (float*)d_out;
    float* y    = out;               // y_pred: [PAIRS, 2]
    float* xout = out + PAIRS * 2;   // x:      [NN, D2]

    int E = in_sizes[1] / 2;
    int ETOT = E + NN;

    __half *p_h1, *p_h2;
    float *p_x1, *p_as1, *p_ad1, *p_as2, *p_ad2;
    cudaGetSymbolAddress((void**)&p_h1, g_h1);
    cudaGetSymbolAddress((void**)&p_x1, g_x1);
    cudaGetSymbolAddress((void**)&p_h2, g_h2);
    cudaGetSymbolAddress((void**)&p_as1, g_as1);
    cudaGetSymbolAddress((void**)&p_ad1, g_ad1);
    cudaGetSymbolAddress((void**)&p_as2, g_as2);
    cudaGetSymbolAddress((void**)&p_ad2, g_ad2);

    static cudaStream_t s2 = nullptr;
    static cudaEvent_t evFork = nullptr, evJoin = nullptr, evA = nullptr, evG = nullptr;
    if (!s2) {
        cudaStreamCreateWithFlags(&s2, cudaStreamNonBlocking);
        cudaEventCreateWithFlags(&evFork, cudaEventDisableTiming);
        cudaEventCreateWithFlags(&evJoin, cudaEventDisableTiming);
        cudaEventCreateWithFlags(&evA, cudaEventDisableTiming);
        cudaEventCreateWithFlags(&evG, cudaEventDisableTiming);
    }

    // fork: CSR build on s2 overlaps GEMM1 + attn1 on main stream
    cudaEventRecord(evFork, 0);
    cudaStreamWaitEvent(s2, evFork, 0);

    k_init_deg<<<(NN + 255) / 256, 256, 0, s2>>>();
    k_count<<<(ETOT + 255) / 256, 256, 0, s2>>>(edge_index, E, ETOT);
    k_scan<<<1, 1024, 0, s2>>>();
    k_scatter<<<(ETOT + 255) / 256, 256, 0, s2>>>(edge_index, E, ETOT);
    cudaEventRecord(evJoin, s2);

    {
        dim3 grid(D1 / 64, (NN + 127) / 128);
        k_gemm_hs<128, 64, 16><<<grid, 256>>>(features, W1, p_h1, NN, FEA, D1);
    }
    k_attn<H1, C1><<<(NN * H1 + 255) / 256, 256>>>(p_h1, attS1, attD1, p_as1, p_ad1);

    cudaStreamWaitEvent(0, evJoin, 0);

    // agg1 lo half, then pipeline: GEMM2-lo on s2 overlaps agg1 hi half
    k_agg<H1, C1><<<(NHALF * 32 + 255) / 256, 256>>>(p_h1, p_as1, p_ad1, b1, p_x1, 0, NHALF);
    cudaEventRecord(evA, 0);
    cudaStreamWaitEvent(s2, evA, 0);
    {
        dim3 grid(D2 / 64, NHALF / 128);
        k_gemm_hs<128, 64, 16><<<grid, 256, 0, s2>>>(p_x1, W2, p_h2, NHALF, D1, D2);
    }
    cudaEventRecord(evG, s2);

    k_agg<H1, C1><<<((NN - NHALF) * 32 + 255) / 256, 256>>>(p_h1, p_as1, p_ad1, b1, p_x1, NHALF, NN - NHALF);
    {
        dim3 grid(D2 / 64, (NN - NHALF + 127) / 128);
        k_gemm_hs<128, 64, 16><<<grid, 256>>>(p_x1 + (long)NHALF * D1, W2,
                                              p_h2 + (long)NHALF * D2, NN - NHALF, D1, D2);
    }
    cudaStreamWaitEvent(0, evG, 0);

    k_attn<H2, C2><<<(NN * H2 + 255) / 256, 256>>>(p_h2, attS2, attD2, p_as2, p_ad2);
    k_agg<H2, C2><<<(NN * 32 + 255) / 256, 256>>>(p_h2, p_as2, p_ad2, b2, xout, 0, NN);

    // Pair head
    k_pair<<<(PAIRS * 32 + 255) / 256, 256>>>(xout, n1, n2, linW, linb, y);
}

// round 10
// speedup vs baseline: 1.4404x; 1.0234x over previous
#include <cuda_runtime.h>
#include <cuda_fp16.h>
#include <cstdint>

#define FULL 0xffffffffu

constexpr int NN   = 50000;
constexpr int FEA  = 213;
constexpr int H1   = 12, C1 = 16, D1 = 192;
constexpr int H2   = 8,  C2 = 8,  D2 = 64;
constexpr int PAIRS = 16384;
constexpr int EMAX = 800000;
constexpr int ETOTMAX = EMAX + NN;
constexpr int NHALF = 25088;   // node split for agg1/GEMM2 pipelining (mult of 128)

// ---------------- device scratch (static, no runtime alloc) ----------------
__device__ __half g_h1[NN * D1];    // layer-1 features, fp16
__device__ __half g_x1h[NN * D1];   // layer-1 output (post elu), fp16
__device__ __half g_h2[NN * D2];    // layer-2 features, fp16
__device__ float  g_as1[NN * H1];
__device__ float  g_ad1[NN * H1];
__device__ float  g_as2[NN * H2];
__device__ float  g_ad2[NN * H2];
__device__ int    g_deg[NN];
__device__ int    g_cursor[NN];
__device__ int    g_rowptr[NN + 1];
__device__ int    g_col[ETOTMAX];

__device__ __forceinline__ float leaky(float x) { return x > 0.f ? x : 0.2f * x; }

// ---------------- CSR build ----------------
__global__ void k_init_deg() {
    int i = blockIdx.x * blockDim.x + threadIdx.x;
    if (i < NN) { g_deg[i] = 0; g_cursor[i] = 0; }
}

__global__ void k_count(const int* __restrict__ ei, int E, int ETOT) {
    int i = blockIdx.x * blockDim.x + threadIdx.x;
    if (i >= ETOT) return;
    int dst = (i < E) ? ei[E + i] : (i - E);
    atomicAdd(&g_deg[dst], 1);
}

__global__ void k_scan() {  // single block, 1024 threads
    __shared__ int s[1024];
    int t = threadIdx.x;
    const int chunk = (NN + 1023) / 1024;
    int start = t * chunk;
    int end = start + chunk; if (end > NN) end = NN; if (start > NN) start = NN;
    int sum = 0;
    for (int i = start; i < end; i++) sum += g_deg[i];
    s[t] = sum;
    __syncthreads();
    for (int off = 1; off < 1024; off <<= 1) {
        int v = 0;
        if (t >= off) v = s[t - off];
        __syncthreads();
        s[t] += v;
        __syncthreads();
    }
    int run = s[t] - sum;  // exclusive prefix
    for (int i = start; i < end; i++) { g_rowptr[i] = run; run += g_deg[i]; }
    if (t == 1023) g_rowptr[NN] = s[1023];
}

__global__ void k_scatter(const int* __restrict__ ei, int E, int ETOT) {
    int i = blockIdx.x * blockDim.x + threadIdx.x;
    if (i >= ETOT) return;
    int src, dst;
    if (i < E) { src = ei[i]; dst = ei[E + i]; }
    else       { src = dst = i - E; }
    int pos = atomicAdd(&g_cursor[dst], 1);
    g_col[g_rowptr[dst] + pos] = src;
}

// ------------- fp16-split (Markidis) tensor-core GEMM, m16n8k16 -------------
__device__ __forceinline__ void split_pair(float x0, float x1,
                                           uint32_t& bg, uint32_t& sm) {
    __half2 b = __floats2half2_rn(x0, x1);
    float2 bf = __half22float2(b);
    __half2 s = __floats2half2_rn(x0 - bf.x, x1 - bf.y);
    bg = *reinterpret_cast<uint32_t*>(&b);
    sm = *reinterpret_cast<uint32_t*>(&s);
}
__device__ __forceinline__ void mma_f16(float* c, const uint32_t* a, const uint32_t* b) {
    asm volatile(
        "mma.sync.aligned.m16n8k16.row.col.f32.f16.f16.f32 "
        "{%0,%1,%2,%3}, {%4,%5,%6,%7}, {%8,%9}, {%0,%1,%2,%3};"
        : "+f"(c[0]), "+f"(c[1]), "+f"(c[2]), "+f"(c[3])
        : "r"(a[0]), "r"(a[1]), "r"(a[2]), "r"(a[3]), "r"(b[0]), "r"(b[1]));
}

// fp32 A, fp32 B, 3-term split (layer 1). C written as __half.
template <int BM, int BN, int BK>
__global__ void __launch_bounds__(256)
k_gemm_hs(const float* __restrict__ A, const float* __restrict__ B,
          __half* __restrict__ Cm, int M, int K, int Nc) {
    constexpr int KP  = BK / 2;
    constexpr int AST = BM + 8;
    constexpr int BST = BN + 8;
    __shared__ uint32_t AsB[2][KP][AST], AsS[2][KP][AST];
    __shared__ uint32_t BsB[2][KP][BST], BsS[2][KP][BST];
    constexpr int ALD = BM * KP / 256;   // 4
    constexpr int BLD = BN * KP / 256;   // 2
    int t = threadIdx.x;
    int lane = t & 31, wid = t >> 5;
    int wm = wid & 3, wn = wid >> 2;
    int cq = lane & 3, gq = lane >> 2;
    int bm = blockIdx.y * BM, bn = blockIdx.x * BN;
    float acc[2][4][4] = {};
    uint32_t rabg[ALD], rasm[ALD], rbbg[BLD], rbsm[BLD];

    #pragma unroll
    for (int u = 0; u < ALD; u++) {
        int i = t + 256 * u;
        int r = i >> 3, kp = i & 7;
        int row = bm + r;
        int k0 = 2 * kp;
        float x0 = (row < M && k0     < K) ? A[(long)row * K + k0]     : 0.f;
        float x1 = (row < M && k0 + 1 < K) ? A[(long)row * K + k0 + 1] : 0.f;
        uint32_t bg, sm;
        split_pair(x0, x1, bg, sm);
        AsB[0][kp][r] = bg; AsS[0][kp][r] = sm;
    }
    #pragma unroll
    for (int u = 0; u < BLD; u++) {
        int i = t + 256 * u;
        int col = i % BN, kp = i / BN;
        int k0 = 2 * kp;
        float x0 = (k0     < K) ? B[(long)k0       * Nc + bn + col] : 0.f;
        float x1 = (k0 + 1 < K) ? B[(long)(k0 + 1) * Nc + bn + col] : 0.f;
        uint32_t bg, sm;
        split_pair(x0, x1, bg, sm);
        BsB[0][kp][col] = bg; BsS[0][kp][col] = sm;
    }
    __syncthreads();

    int nTiles = (K + BK - 1) / BK;
    for (int tile = 0; tile < nTiles; tile++) {
        int buf = tile & 1;
        int k0n = (tile + 1) * BK;
        if (tile + 1 < nTiles) {
            #pragma unroll
            for (int u = 0; u < ALD; u++) {
                int i = t + 256 * u;
                int r = i >> 3, kp = i & 7;
                int row = bm + r;
                int k0 = k0n + 2 * kp;
                float x0 = (row < M && k0     < K) ? A[(long)row * K + k0]     : 0.f;
                float x1 = (row < M && k0 + 1 < K) ? A[(long)row * K + k0 + 1] : 0.f;
                split_pair(x0, x1, rabg[u], rasm[u]);
            }
            #pragma unroll
            for (int u = 0; u < BLD; u++) {
                int i = t + 256 * u;
                int col = i % BN, kp = i / BN;
                int k0 = k0n + 2 * kp;
                float x0 = (k0     < K) ? B[(long)k0       * Nc + bn + col] : 0.f;
                float x1 = (k0 + 1 < K) ? B[(long)(k0 + 1) * Nc + bn + col] : 0.f;
                split_pair(x0, x1, rbbg[u], rbsm[u]);
            }
        }
        {
            uint32_t ab[2][4], as_[2][4];
            #pragma unroll
            for (int mt = 0; mt < 2; mt++) {
                int row = wm * 32 + mt * 16 + gq;
                ab[mt][0]  = AsB[buf][cq][row];     ab[mt][1]  = AsB[buf][cq][row + 8];
                ab[mt][2]  = AsB[buf][cq + 4][row]; ab[mt][3]  = AsB[buf][cq + 4][row + 8];
                as_[mt][0] = AsS[buf][cq][row];     as_[mt][1] = AsS[buf][cq][row + 8];
                as_[mt][2] = AsS[buf][cq + 4][row]; as_[mt][3] = AsS[buf][cq + 4][row + 8];
            }
            uint32_t bb[4][2], bs[4][2];
            #pragma unroll
            for (int nt = 0; nt < 4; nt++) {
                int col = wn * 32 + nt * 8 + gq;
                bb[nt][0] = BsB[buf][cq][col]; bb[nt][1] = BsB[buf][cq + 4][col];
                bs[nt][0] = BsS[buf][cq][col]; bs[nt][1] = BsS[buf][cq + 4][col];
            }
            #pragma unroll
            for (int mt = 0; mt < 2; mt++)
                #pragma unroll
                for (int nt = 0; nt < 4; nt++) {
                    mma_f16(acc[mt][nt], as_[mt], bb[nt]);
                    mma_f16(acc[mt][nt], ab[mt],  bs[nt]);
                    mma_f16(acc[mt][nt], ab[mt],  bb[nt]);
                }
        }
        if (tile + 1 < nTiles) {
            __syncthreads();
            int nb = buf ^ 1;
            #pragma unroll
            for (int u = 0; u < ALD; u++) {
                int i = t + 256 * u;
                int r = i >> 3, kp = i & 7;
                AsB[nb][kp][r] = rabg[u]; AsS[nb][kp][r] = rasm[u];
            }
            #pragma unroll
            for (int u = 0; u < BLD; u++) {
                int i = t + 256 * u;
                int col = i % BN, kp = i / BN;
                BsB[nb][kp][col] = rbbg[u]; BsS[nb][kp][col] = rbsm[u];
            }
            __syncthreads();
        }
    }
    #pragma unroll
    for (int mt = 0; mt < 2; mt++) {
        int row0 = bm + wm * 32 + mt * 16 + gq;
        #pragma unroll
        for (int nt = 0; nt < 4; nt++) {
            int col = bn + wn * 32 + nt * 8 + 2 * cq;
            if (row0 < M)
                *(__half2*)&Cm[(long)row0 * Nc + col] =
                    __floats2half2_rn(acc[mt][nt][0], acc[mt][nt][1]);
            if (row0 + 8 < M)
                *(__half2*)&Cm[(long)(row0 + 8) * Nc + col] =
                    __floats2half2_rn(acc[mt][nt][2], acc[mt][nt][3]);
        }
    }
}

// fp16 A (exact, no small plane), fp32 B split -> 2-term MMA (layer 2).
template <int BM, int BN, int BK>
__global__ void __launch_bounds__(256)
k_gemm_h16(const __half* __restrict__ A, const float* __restrict__ B,
           __half* __restrict__ Cm, int M, int K, int Nc) {
    constexpr int KP  = BK / 2;
    constexpr int AST = BM + 8;
    constexpr int BST = BN + 8;
    __shared__ uint32_t AsB[2][KP][AST];
    __shared__ uint32_t BsB[2][KP][BST], BsS[2][KP][BST];
    constexpr int ALD = BM * KP / 256;   // 4
    constexpr int BLD = BN * KP / 256;   // 2
    int t = threadIdx.x;
    int lane = t & 31, wid = t >> 5;
    int wm = wid & 3, wn = wid >> 2;
    int cq = lane & 3, gq = lane >> 2;
    int bm = blockIdx.y * BM, bn = blockIdx.x * BN;
    float acc[2][4][4] = {};
    uint32_t rabg[ALD], rbbg[BLD], rbsm[BLD];

    #pragma unroll
    for (int u = 0; u < ALD; u++) {
        int i = t + 256 * u;
        int r = i >> 3, kp = i & 7;
        int row = bm + r;
        int k0 = 2 * kp;
        uint32_t va = 0;
        if (row < M && k0 + 1 < K) va = *(const uint32_t*)&A[(long)row * K + k0];
        AsB[0][kp][r] = va;
    }
    #pragma unroll
    for (int u = 0; u < BLD; u++) {
        int i = t + 256 * u;
        int col = i % BN, kp = i / BN;
        int k0 = 2 * kp;
        float x0 = (k0     < K) ? B[(long)k0       * Nc + bn + col] : 0.f;
        float x1 = (k0 + 1 < K) ? B[(long)(k0 + 1) * Nc + bn + col] : 0.f;
        uint32_t bg, sm;
        split_pair(x0, x1, bg, sm);
        BsB[0][kp][col] = bg; BsS[0][kp][col] = sm;
    }
    __syncthreads();

    int nTiles = (K + BK - 1) / BK;
    for (int tile = 0; tile < nTiles; tile++) {
        int buf = tile & 1;
        int k0n = (tile + 1) * BK;
        if (tile + 1 < nTiles) {
            #pragma unroll
            for (int u = 0; u < ALD; u++) {
                int i = t + 256 * u;
                int r = i >> 3, kp = i & 7;
                int row = bm + r;
                int k0 = k0n + 2 * kp;
                uint32_t va = 0;
                if (row < M && k0 + 1 < K) va = *(const uint32_t*)&A[(long)row * K + k0];
                rabg[u] = va;
            }
            #pragma unroll
            for (int u = 0; u < BLD; u++) {
                int i = t + 256 * u;
                int col = i % BN, kp = i / BN;
                int k0 = k0n + 2 * kp;
                float x0 = (k0     < K) ? B[(long)k0       * Nc + bn + col] : 0.f;
                float x1 = (k0 + 1 < K) ? B[(long)(k0 + 1) * Nc + bn + col] : 0.f;
                split_pair(x0, x1, rbbg[u], rbsm[u]);
            }
        }
        {
            uint32_t ab[2][4];
            #pragma unroll
            for (int mt = 0; mt < 2; mt++) {
                int row = wm * 32 + mt * 16 + gq;
                ab[mt][0] = AsB[buf][cq][row];     ab[mt][1] = AsB[buf][cq][row + 8];
                ab[mt][2] = AsB[buf][cq + 4][row]; ab[mt][3] = AsB[buf][cq + 4][row + 8];
            }
            uint32_t bb[4][2], bs[4][2];
            #pragma unroll
            for (int nt = 0; nt < 4; nt++) {
                int col = wn * 32 + nt * 8 + gq;
                bb[nt][0] = BsB[buf][cq][col]; bb[nt][1] = BsB[buf][cq + 4][col];
                bs[nt][0] = BsS[buf][cq][col]; bs[nt][1] = BsS[buf][cq + 4][col];
            }
            #pragma unroll
            for (int mt = 0; mt < 2; mt++)
                #pragma unroll
                for (int nt = 0; nt < 4; nt++) {
                    mma_f16(acc[mt][nt], ab[mt], bs[nt]);
                    mma_f16(acc[mt][nt], ab[mt], bb[nt]);
                }
        }
        if (tile + 1 < nTiles) {
            __syncthreads();
            int nb = buf ^ 1;
            #pragma unroll
            for (int u = 0; u < ALD; u++) {
                int i = t + 256 * u;
                int r = i >> 3, kp = i & 7;
                AsB[nb][kp][r] = rabg[u];
            }
            #pragma unroll
            for (int u = 0; u < BLD; u++) {
                int i = t + 256 * u;
                int col = i % BN, kp = i / BN;
                BsB[nb][kp][col] = rbbg[u]; BsS[nb][kp][col] = rbsm[u];
            }
            __syncthreads();
        }
    }
    #pragma unroll
    for (int mt = 0; mt < 2; mt++) {
        int row0 = bm + wm * 32 + mt * 16 + gq;
        #pragma unroll
        for (int nt = 0; nt < 4; nt++) {
            int col = bn + wn * 32 + nt * 8 + 2 * cq;
            if (row0 < M)
                *(__half2*)&Cm[(long)row0 * Nc + col] =
                    __floats2half2_rn(acc[mt][nt][0], acc[mt][nt][1]);
            if (row0 + 8 < M)
                *(__half2*)&Cm[(long)(row0 + 8) * Nc + col] =
                    __floats2half2_rn(acc[mt][nt][2], acc[mt][nt][3]);
        }
    }
}

// ---------------- attention scores a_src, a_dst (half2 features) ------------
template <int H, int C>
__global__ void k_attn(const __half* __restrict__ h, const float* __restrict__ aS,
                       const float* __restrict__ aD, float* __restrict__ s_,
                       float* __restrict__ d_) {
    int i = blockIdx.x * blockDim.x + threadIdx.x;
    if (i >= NN * H) return;
    int n = i / H, hh = i % H;
    const __half2* hp = (const __half2*)(h + (long)n * H * C + hh * C);
    float s = 0.f, d = 0.f;
    #pragma unroll
    for (int c = 0; c < C / 2; c++) {
        float2 v = __half22float2(hp[c]);
        s += v.x * aS[hh * C + 2 * c] + v.y * aS[hh * C + 2 * c + 1];
        d += v.x * aD[hh * C + 2 * c] + v.y * aD[hh * C + 2 * c + 1];
    }
    s_[i] = s; d_[i] = d;
}

// ---------------- layer-1 aggregation: one LDG.128 per edge -----------------
// Lane l (<24) owns 8 consecutive halves (16B) of the 384B row; head = l>>1.
// Max-free softmax; lane hh (<12) accumulates denom of head hh. fp16 output.
__device__ __forceinline__ void acc8(float* acc, uint4 v, float w) {
    __half2* hv = reinterpret_cast<__half2*>(&v);
    #pragma unroll
    for (int q = 0; q < 4; q++) {
        float2 f = __half22float2(hv[q]);
        acc[2 * q]     += w * f.x;
        acc[2 * q + 1] += w * f.y;
    }
}

__global__ void k_agg1(const __half* __restrict__ h, const float* __restrict__ as_,
                       const float* __restrict__ ad_, const float* __restrict__ bias,
                       __half* __restrict__ out, int n0, int cnt) {
    constexpr int H = H1, D = D1;
    int warp = (blockIdx.x * blockDim.x + threadIdx.x) >> 5;
    int lane = threadIdx.x & 31;
    if (warp >= cnt) return;
    int node = n0 + warp;
    int r0 = g_rowptr[node];
    int r1 = g_rowptr[node + 1];

    float adv = (lane < H) ? ad_[node * H + lane] : 0.f;
    int myHead = (lane < 24) ? (lane >> 1) : 0;

    float acc[8] = {};
    float denom = 0.f;
    int j = r0;
    for (; j + 3 < r1; j += 4) {
        int s0 = g_col[j], s1 = g_col[j + 1], s2 = g_col[j + 2], s3 = g_col[j + 3];
        float w0 = 0.f, w1 = 0.f, w2 = 0.f, w3 = 0.f;
        if (lane < H) {
            w0 = __expf(leaky(__ldg(as_ + (long)s0 * H + lane) + adv));
            w1 = __expf(leaky(__ldg(as_ + (long)s1 * H + lane) + adv));
            w2 = __expf(leaky(__ldg(as_ + (long)s2 * H + lane) + adv));
            w3 = __expf(leaky(__ldg(as_ + (long)s3 * H + lane) + adv));
            denom += (w0 + w1) + (w2 + w3);
        }
        float e0 = __shfl_sync(FULL, w0, myHead);
        float e1 = __shfl_sync(FULL, w1, myHead);
        float e2 = __shfl_sync(FULL, w2, myHead);
        float e3 = __shfl_sync(FULL, w3, myHead);
        if (lane < 24) {
            uint4 v0 = *(const uint4*)(h + (long)s0 * D + lane * 8);
            uint4 v1 = *(const uint4*)(h + (long)s1 * D + lane * 8);
            uint4 v2 = *(const uint4*)(h + (long)s2 * D + lane * 8);
            uint4 v3 = *(const uint4*)(h + (long)s3 * D + lane * 8);
            acc8(acc, v0, e0);
            acc8(acc, v1, e1);
            acc8(acc, v2, e2);
            acc8(acc, v3, e3);
        }
    }
    for (; j < r1; j++) {
        int s0 = g_col[j];
        float w0 = 0.f;
        if (lane < H) {
            w0 = __expf(leaky(__ldg(as_ + (long)s0 * H + lane) + adv));
            denom += w0;
        }
        float e0 = __shfl_sync(FULL, w0, myHead);
        if (lane < 24) {
            uint4 v0 = *(const uint4*)(h + (long)s0 * D + lane * 8);
            acc8(acc, v0, e0);
        }
    }

    float rden = __frcp_rn(denom);
    float rk = __shfl_sync(FULL, rden, myHead);
    if (lane < 24) {
        int off = lane * 8;
        const float4* bp = (const float4*)&bias[off];
        float4 b0 = bp[0], b1 = bp[1];
        float v[8];
        v[0] = acc[0] * rk + b0.x; v[1] = acc[1] * rk + b0.y;
        v[2] = acc[2] * rk + b0.z; v[3] = acc[3] * rk + b0.w;
        v[4] = acc[4] * rk + b1.x; v[5] = acc[5] * rk + b1.y;
        v[6] = acc[6] * rk + b1.z; v[7] = acc[7] * rk + b1.w;
        #pragma unroll
        for (int q = 0; q < 8; q++)
            v[q] = v[q] > 0.f ? v[q] : __expf(v[q]) - 1.f;
        uint4 pk;
        __half2* ph = reinterpret_cast<__half2*>(&pk);
        ph[0] = __floats2half2_rn(v[0], v[1]);
        ph[1] = __floats2half2_rn(v[2], v[3]);
        ph[2] = __floats2half2_rn(v[4], v[5]);
        ph[3] = __floats2half2_rn(v[6], v[7]);
        *(uint4*)(out + (long)node * D + off) = pk;
    }
}

// ---------------- layer-2 aggregation (half2 gather, fp32 out) --------------
template <int H, int C>
__global__ void k_agg(const __half* __restrict__ h, const float* __restrict__ as_,
                      const float* __restrict__ ad_, const float* __restrict__ bias,
                      float* __restrict__ out, int n0, int cnt) {
    constexpr int D = H * C;
    constexpr int PER2 = D / 64;
    int warp = (blockIdx.x * blockDim.x + threadIdx.x) >> 5;
    int lane = threadIdx.x & 31;
    if (warp >= cnt) return;
    int node = n0 + warp;
    int r0 = g_rowptr[node];
    int r1 = g_rowptr[node + 1];

    float adv = (lane < H) ? ad_[node * H + lane] : 0.f;

    float2 acc[PER2];
    #pragma unroll
    for (int i = 0; i < PER2; i++) acc[i] = make_float2(0.f, 0.f);
    float denom = 0.f;
    int j = r0;
    for (; j + 3 < r1; j += 4) {
        int s0 = g_col[j], s1 = g_col[j + 1], s2 = g_col[j + 2], s3 = g_col[j + 3];
        float w0 = 0.f, w1 = 0.f, w2 = 0.f, w3 = 0.f;
        if (lane < H) {
            w0 = __expf(leaky(__ldg(as_ + (long)s0 * H + lane) + adv));
            w1 = __expf(leaky(__ldg(as_ + (long)s1 * H + lane) + adv));
            w2 = __expf(leaky(__ldg(as_ + (long)s2 * H + lane) + adv));
            w3 = __expf(leaky(__ldg(as_ + (long)s3 * H + lane) + adv));
            denom += (w0 + w1) + (w2 + w3);
        }
        const __half2* h0 = (const __half2*)(h + (long)s0 * D);
        const __half2* h1 = (const __half2*)(h + (long)s1 * D);
        const __half2* h2 = (const __half2*)(h + (long)s2 * D);
        const __half2* h3 = (const __half2*)(h + (long)s3 * D);
        #pragma unroll
        for (int i = 0; i < PER2; i++) {
            int k2 = 2 * lane + 64 * i;
            int p  = lane + 32 * i;
            int sl = k2 / C;
            float wa = __shfl_sync(FULL, w0, sl);
            float wb = __shfl_sync(FULL, w1, sl);
            float wc = __shfl_sync(FULL, w2, sl);
            float wd = __shfl_sync(FULL, w3, sl);
            float2 v0 = __half22float2(h0[p]);
            float2 v1 = __half22float2(h1[p]);
            float2 v2 = __half22float2(h2[p]);
            float2 v3 = __half22float2(h3[p]);
            acc[i].x += wa * v0.x + wb * v1.x + wc * v2.x + wd * v3.x;
            acc[i].y += wa * v0.y + wb * v1.y + wc * v2.y + wd * v3.y;
        }
    }
    for (; j < r1; j++) {
        int s0 = g_col[j];
        float w0 = 0.f;
        if (lane < H) {
            w0 = __expf(leaky(__ldg(as_ + (long)s0 * H + lane) + adv));
            denom += w0;
        }
        const __half2* h0 = (const __half2*)(h + (long)s0 * D);
        #pragma unroll
        for (int i = 0; i < PER2; i++) {
            int k2 = 2 * lane + 64 * i;
            int p  = lane + 32 * i;
            float wa = __shfl_sync(FULL, w0, k2 / C);
            float2 v0 = __half22float2(h0[p]);
            acc[i].x += wa * v0.x;
            acc[i].y += wa * v0.y;
        }
    }

    float rden = __frcp_rn(denom);
    #pragma unroll
    for (int i = 0; i < PER2; i++) {
        int k2 = 2 * lane + 64 * i;
        float rk = __shfl_sync(FULL, rden, k2 / C);
        float2 bv = *(const float2*)&bias[k2];
        float vx = acc[i].x * rk + bv.x;
        float vy = acc[i].y * rk + bv.y;
        vx = vx > 0.f ? vx : __expf(vx) - 1.f;
        vy = vy > 0.f ? vy : __expf(vy) - 1.f;
        *(float2*)&out[(long)node * D + k2] = make_float2(vx, vy);
    }
}

// ---------------- pair scoring head ----------------
__global__ void k_pair(const float* __restrict__ x, const int* __restrict__ n1,
                       const int* __restrict__ n2, const float* __restrict__ linW,
                       const float* __restrict__ linb, float* __restrict__ y) {
    int warp = (blockIdx.x * blockDim.x + threadIdx.x) >> 5;
    int lane = threadIdx.x & 31;
    if (warp >= PAIRS) return;
    int a = n1[warp], b = n2[warp];
    float p0 = 0.f, p1 = 0.f;
    #pragma unroll
    for (int i = 0; i < 4; i++) {
        int k = lane + 32 * i;
        float xv = (k < D2) ? x[(long)a * D2 + k] : x[(long)b * D2 + (k - D2)];
        p0 += xv * linW[k * 2 + 0];
        p1 += xv * linW[k * 2 + 1];
    }
    #pragma unroll
    for (int off = 16; off; off >>= 1) {
        p0 += __shfl_xor_sync(FULL, p0, off);
        p1 += __shfl_xor_sync(FULL, p1, off);
    }
    if (lane == 0) {
        float z0 = p0 + linb[0], z1 = p1 + linb[1];
        y[warp * 2 + 0] = 1.f / (1.f + __expf(-z0));
        y[warp * 2 + 1] = 1.f / (1.f + __expf(-z1));
    }
}

// ---------------- launcher with fork/join + agg1/GEMM2 pipelining ----------
extern "C" void kernel_launch(void* const* d_in, const int* in_sizes, int n_in,
                              void* d_out, int out_size) {
    const float* features = (const float*)d_in[0];
    const int*   edge_index = (const int*)d_in[1];
    const int*   n1 = (const int*)d_in[2];
    const int*   n2 = (const int*)d_in[3];
    const float* W1 = (const float*)d_in[4];
    const float* attS1 = (const float*)d_in[5];
    const float* attD1 = (const float*)d_in[6];
    const float* b1 = (const float*)d_in[7];
    const float* W2 = (const float*)d_in[8];
    const float* attS2 = (const float*)d_in[9];
    const float* attD2 = (const float*)d_in[10];
    const float* b2 = (const float*)d_in[11];
    const float* linW = (const float*)d_in[12];
    const float* linb = (const float*)d_in[13];

    float* out  = (float*)d_out;
    float* y    = out;               // y_pred: [PAIRS, 2]
    float* xout = out + PAIRS * 2;   // x:      [NN, D2]

    int E = in_sizes[1] / 2;
    int ETOT = E + NN;

    __half *p_h1, *p_x1h, *p_h2;
    float *p_as1, *p_ad1, *p_as2, *p_ad2;
    cudaGetSymbolAddress((void**)&p_h1, g_h1);
    cudaGetSymbolAddress((void**)&p_x1h, g_x1h);
    cudaGetSymbolAddress((void**)&p_h2, g_h2);
    cudaGetSymbolAddress((void**)&p_as1, g_as1);
    cudaGetSymbolAddress((void**)&p_ad1, g_ad1);
    cudaGetSymbolAddress((void**)&p_as2, g_as2);
    cudaGetSymbolAddress((void**)&p_ad2, g_ad2);

    static cudaStream_t s2 = nullptr;
    static cudaEvent_t evFork = nullptr, evJoin = nullptr, evA = nullptr, evG = nullptr;
    if (!s2) {
        cudaStreamCreateWithFlags(&s2, cudaStreamNonBlocking);
        cudaEventCreateWithFlags(&evFork, cudaEventDisableTiming);
        cudaEventCreateWithFlags(&evJoin, cudaEventDisableTiming);
        cudaEventCreateWithFlags(&evA, cudaEventDisableTiming);
        cudaEventCreateWithFlags(&evG, cudaEventDisableTiming);
    }

    // fork: CSR build on s2 overlaps GEMM1 + attn1 on main stream
    cudaEventRecord(evFork, 0);
    cudaStreamWaitEvent(s2, evFork, 0);

    k_init_deg<<<(NN + 255) / 256, 256, 0, s2>>>();
    k_count<<<(ETOT + 255) / 256, 256, 0, s2>>>(edge_index, E, ETOT);
    k_scan<<<1, 1024, 0, s2>>>();
    k_scatter<<<(ETOT + 255) / 256, 256, 0, s2>>>(edge_index, E, ETOT);
    cudaEventRecord(evJoin, s2);

    {
        dim3 grid(D1 / 64, (NN + 127) / 128);
        k_gemm_hs<128, 64, 16><<<grid, 256>>>(features, W1, p_h1, NN, FEA, D1);
    }
    k_attn<H1, C1><<<(NN * H1 + 255) / 256, 256>>>(p_h1, attS1, attD1, p_as1, p_ad1);

    cudaStreamWaitEvent(0, evJoin, 0);

    // agg1 lo half, then pipeline: GEMM2-lo on s2 overlaps agg1 hi half
    k_agg1<<<(NHALF * 32 + 255) / 256, 256>>>(p_h1, p_as1, p_ad1, b1, p_x1h, 0, NHALF);
    cudaEventRecord(evA, 0);
    cudaStreamWaitEvent(s2, evA, 0);
    {
        dim3 grid(D2 / 64, NHALF / 128);
        k_gemm_h16<128, 64, 16><<<grid, 256, 0, s2>>>(p_x1h, W2, p_h2, NHALF, D1, D2);
    }
    cudaEventRecord(evG, s2);

    k_agg1<<<((NN - NHALF) * 32 + 255) / 256, 256>>>(p_h1, p_as1, p_ad1, b1, p_x1h, NHALF, NN - NHALF);
    {
        dim3 grid(D2 / 64, (NN - NHALF + 127) / 128);
        k_gemm_h16<128, 64, 16><<<grid, 256>>>(p_x1h + (long)NHALF * D1, W2,
                                               p_h2 + (long)NHALF * D2, NN - NHALF, D1, D2);
    }
    cudaStreamWaitEvent(0, evG, 0);

    k_attn<H2, C2><<<(NN * H2 + 255) / 256, 256>>>(p_h2, attS2, attD2, p_as2, p_ad2);
    k_agg<H2, C2><<<(NN * 32 + 255) / 256, 256>>>(p_h2, p_as2, p_ad2, b2, xout, 0, NN);

    // Pair head
    k_pair<<<(PAIRS * 32 + 255) / 256, 256>>>(xout, n1, n2, linW, linb, y);
}

// round 11
// speedup vs baseline: 1.5487x; 1.0751x over previous
#include <cuda_runtime.h>
#include <cuda_fp16.h>
#include <cstdint>

#define FULL 0xffffffffu

constexpr int NN   = 50000;
constexpr int FEA  = 213;
constexpr int H1   = 12, C1 = 16, D1 = 192;
constexpr int H2   = 8,  C2 = 8,  D2 = 64;
constexpr int PAIRS = 16384;
constexpr int EMAX = 800000;
constexpr int NHALF = 25088;   // node split for agg1/GEMM2 pipelining (mult of 128)

// ---------------- device scratch (static, no runtime alloc) ----------------
__device__ __half g_h1[NN * D1];
__device__ __half g_x1h[NN * D1];
__device__ __half g_h2[NN * D2];
__device__ float  g_as1[NN * H1];
__device__ float  g_ad1[NN * H1];
__device__ float  g_as2[NN * H2];
__device__ float  g_ad2[NN * H2];
__device__ __align__(16) int g_deg[NN];
__device__ int    g_cursor[NN];
__device__ int    g_rowptr[NN + 1];
__device__ int    g_col[EMAX];

__device__ __forceinline__ float leaky(float x) { return x > 0.f ? x : 0.2f * x; }

// ---------------- CSR build (edges only; self-loops implicit) ---------------
__global__ void k_init_deg() {
    int i = blockIdx.x * blockDim.x + threadIdx.x;
    if (i < NN) { g_deg[i] = 0; g_cursor[i] = 0; }
}

__global__ void k_count(const int* __restrict__ ei, int E) {
    int i4 = (blockIdx.x * blockDim.x + threadIdx.x) * 4;
    if (i4 + 3 < E) {
        int4 d = *(const int4*)(ei + E + i4);
        atomicAdd(&g_deg[d.x], 1);
        atomicAdd(&g_deg[d.y], 1);
        atomicAdd(&g_deg[d.z], 1);
        atomicAdd(&g_deg[d.w], 1);
    } else {
        for (int i = i4; i < E; i++) atomicAdd(&g_deg[ei[E + i]], 1);
    }
}

__global__ void k_scan() {  // single block, 1024 threads
    __shared__ int s[1024];
    int t = threadIdx.x;
    const int chunk = 52;   // multiple of 4 for int4 loads
    int start = t * chunk;
    int end = start + chunk; if (end > NN) end = NN; if (start > NN) start = NN;
    int sum = 0;
    if (start < NN) {
        int full = (end - start) / 4;
        const int4* p = (const int4*)(g_deg + start);
        for (int i = 0; i < full; i++) { int4 v = p[i]; sum += v.x + v.y + v.z + v.w; }
        for (int i = start + full * 4; i < end; i++) sum += g_deg[i];
    }
    s[t] = sum;
    __syncthreads();
    for (int off = 1; off < 1024; off <<= 1) {
        int v = 0;
        if (t >= off) v = s[t - off];
        __syncthreads();
        s[t] += v;
        __syncthreads();
    }
    int run = s[t] - sum;  // exclusive prefix
    for (int i = start; i < end; i++) { g_rowptr[i] = run; run += g_deg[i]; }
    if (t == 1023) g_rowptr[NN] = s[1023];
}

__global__ void k_scatter(const int* __restrict__ ei, int E) {
    int i4 = (blockIdx.x * blockDim.x + threadIdx.x) * 4;
    if (i4 + 3 < E) {
        int4 sv = *(const int4*)(ei + i4);
        int4 dv = *(const int4*)(ei + E + i4);
        int p0 = atomicAdd(&g_cursor[dv.x], 1); g_col[g_rowptr[dv.x] + p0] = sv.x;
        int p1 = atomicAdd(&g_cursor[dv.y], 1); g_col[g_rowptr[dv.y] + p1] = sv.y;
        int p2 = atomicAdd(&g_cursor[dv.z], 1); g_col[g_rowptr[dv.z] + p2] = sv.z;
        int p3 = atomicAdd(&g_cursor[dv.w], 1); g_col[g_rowptr[dv.w] + p3] = sv.w;
    } else {
        for (int i = i4; i < E; i++) {
            int src = ei[i], dst = ei[E + i];
            int pos = atomicAdd(&g_cursor[dst], 1);
            g_col[g_rowptr[dst] + pos] = src;
        }
    }
}

// ------------- fp16-split (Markidis) tensor-core GEMM, m16n8k16 -------------
__device__ __forceinline__ void split_pair(float x0, float x1,
                                           uint32_t& bg, uint32_t& sm) {
    __half2 b = __floats2half2_rn(x0, x1);
    float2 bf = __half22float2(b);
    __half2 s = __floats2half2_rn(x0 - bf.x, x1 - bf.y);
    bg = *reinterpret_cast<uint32_t*>(&b);
    sm = *reinterpret_cast<uint32_t*>(&s);
}
__device__ __forceinline__ void mma_f16(float* c, const uint32_t* a, const uint32_t* b) {
    asm volatile(
        "mma.sync.aligned.m16n8k16.row.col.f32.f16.f16.f32 "
        "{%0,%1,%2,%3}, {%4,%5,%6,%7}, {%8,%9}, {%0,%1,%2,%3};"
        : "+f"(c[0]), "+f"(c[1]), "+f"(c[2]), "+f"(c[3])
        : "r"(a[0]), "r"(a[1]), "r"(a[2]), "r"(a[3]), "r"(b[0]), "r"(b[1]));
}

// fp32 A, fp32 B, 3-term split (layer 1). C as __half.
// Fused attention epilogue: CTA's 64 cols = 4 whole heads (C1=16);
// a_src/a_dst computed from fp32 accumulators via quad shuffles.
template <int BM, int BN, int BK>
__global__ void __launch_bounds__(256)
k_gemm_hs(const float* __restrict__ A, const float* __restrict__ B,
          __half* __restrict__ Cm, int M, int K, int Nc,
          const float* __restrict__ aS, const float* __restrict__ aD,
          float* __restrict__ s_, float* __restrict__ d_) {
    constexpr int KP  = BK / 2;
    constexpr int AST = BM + 8;
    constexpr int BST = BN + 8;
    __shared__ uint32_t AsB[2][KP][AST], AsS[2][KP][AST];
    __shared__ uint32_t BsB[2][KP][BST], BsS[2][KP][BST];
    __shared__ float sAS[BN], sAD[BN];
    constexpr int ALD = BM * KP / 256;   // 4
    constexpr int BLD = BN * KP / 256;   // 2
    int t = threadIdx.x;
    int lane = t & 31, wid = t >> 5;
    int wm = wid & 3, wn = wid >> 2;
    int cq = lane & 3, gq = lane >> 2;
    int bm = blockIdx.y * BM, bn = blockIdx.x * BN;
    float acc[2][4][4] = {};
    uint32_t rabg[ALD], rasm[ALD], rbbg[BLD], rbsm[BLD];

    if (t < BN) { sAS[t] = aS[bn + t]; sAD[t] = aD[bn + t]; }

    #pragma unroll
    for (int u = 0; u < ALD; u++) {
        int i = t + 256 * u;
        int r = i >> 3, kp = i & 7;
        int row = bm + r;
        int k0 = 2 * kp;
        float x0 = (row < M && k0     < K) ? A[(long)row * K + k0]     : 0.f;
        float x1 = (row < M && k0 + 1 < K) ? A[(long)row * K + k0 + 1] : 0.f;
        uint32_t bg, sm;
        split_pair(x0, x1, bg, sm);
        AsB[0][kp][r] = bg; AsS[0][kp][r] = sm;
    }
    #pragma unroll
    for (int u = 0; u < BLD; u++) {
        int i = t + 256 * u;
        int col = i % BN, kp = i / BN;
        int k0 = 2 * kp;
        float x0 = (k0     < K) ? B[(long)k0       * Nc + bn + col] : 0.f;
        float x1 = (k0 + 1 < K) ? B[(long)(k0 + 1) * Nc + bn + col] : 0.f;
        uint32_t bg, sm;
        split_pair(x0, x1, bg, sm);
        BsB[0][kp][col] = bg; BsS[0][kp][col] = sm;
    }
    __syncthreads();

    int nTiles = (K + BK - 1) / BK;
    for (int tile = 0; tile < nTiles; tile++) {
        int buf = tile & 1;
        int k0n = (tile + 1) * BK;
        if (tile + 1 < nTiles) {
            #pragma unroll
            for (int u = 0; u < ALD; u++) {
                int i = t + 256 * u;
                int r = i >> 3, kp = i & 7;
                int row = bm + r;
                int k0 = k0n + 2 * kp;
                float x0 = (row < M && k0     < K) ? A[(long)row * K + k0]     : 0.f;
                float x1 = (row < M && k0 + 1 < K) ? A[(long)row * K + k0 + 1] : 0.f;
                split_pair(x0, x1, rabg[u], rasm[u]);
            }
            #pragma unroll
            for (int u = 0; u < BLD; u++) {
                int i = t + 256 * u;
                int col = i % BN, kp = i / BN;
                int k0 = k0n + 2 * kp;
                float x0 = (k0     < K) ? B[(long)k0       * Nc + bn + col] : 0.f;
                float x1 = (k0 + 1 < K) ? B[(long)(k0 + 1) * Nc + bn + col] : 0.f;
                split_pair(x0, x1, rbbg[u], rbsm[u]);
            }
        }
        {
            uint32_t ab[2][4], as_r[2][4];
            #pragma unroll
            for (int mt = 0; mt < 2; mt++) {
                int row = wm * 32 + mt * 16 + gq;
                ab[mt][0]   = AsB[buf][cq][row];     ab[mt][1]   = AsB[buf][cq][row + 8];
                ab[mt][2]   = AsB[buf][cq + 4][row]; ab[mt][3]   = AsB[buf][cq + 4][row + 8];
                as_r[mt][0] = AsS[buf][cq][row];     as_r[mt][1] = AsS[buf][cq][row + 8];
                as_r[mt][2] = AsS[buf][cq + 4][row]; as_r[mt][3] = AsS[buf][cq + 4][row + 8];
            }
            uint32_t bb[4][2], bs[4][2];
            #pragma unroll
            for (int nt = 0; nt < 4; nt++) {
                int col = wn * 32 + nt * 8 + gq;
                bb[nt][0] = BsB[buf][cq][col]; bb[nt][1] = BsB[buf][cq + 4][col];
                bs[nt][0] = BsS[buf][cq][col]; bs[nt][1] = BsS[buf][cq + 4][col];
            }
            #pragma unroll
            for (int mt = 0; mt < 2; mt++)
                #pragma unroll
                for (int nt = 0; nt < 4; nt++) {
                    mma_f16(acc[mt][nt], as_r[mt], bb[nt]);
                    mma_f16(acc[mt][nt], ab[mt],   bs[nt]);
                    mma_f16(acc[mt][nt], ab[mt],   bb[nt]);
                }
        }
        if (tile + 1 < nTiles) {
            __syncthreads();
            int nb = buf ^ 1;
            #pragma unroll
            for (int u = 0; u < ALD; u++) {
                int i = t + 256 * u;
                int r = i >> 3, kp = i & 7;
                AsB[nb][kp][r] = rabg[u]; AsS[nb][kp][r] = rasm[u];
            }
            #pragma unroll
            for (int u = 0; u < BLD; u++) {
                int i = t + 256 * u;
                int col = i % BN, kp = i / BN;
                BsB[nb][kp][col] = rbbg[u]; BsS[nb][kp][col] = rbsm[u];
            }
            __syncthreads();
        }
    }
    // epilogue: write h (fp16) + fused attention scores (fp32 acc)
    #pragma unroll
    for (int mt = 0; mt < 2; mt++) {
        int row0 = bm + wm * 32 + mt * 16 + gq;
        #pragma unroll
        for (int nt = 0; nt < 4; nt++) {
            int col = bn + wn * 32 + nt * 8 + 2 * cq;
            if (row0 < M)
                *(__half2*)&Cm[(long)row0 * Nc + col] =
                    __floats2half2_rn(acc[mt][nt][0], acc[mt][nt][1]);
            if (row0 + 8 < M)
                *(__half2*)&Cm[(long)(row0 + 8) * Nc + col] =
                    __floats2half2_rn(acc[mt][nt][2], acc[mt][nt][3]);
        }
        #pragma unroll
        for (int m = 0; m < 2; m++) {   // 2 heads per warp (16 cols each)
            float sl = 0.f, dl = 0.f, sh = 0.f, dh = 0.f;
            #pragma unroll
            for (int p = 0; p < 2; p++) {
                int nt = 2 * m + p;
                int cl = wn * 32 + nt * 8 + 2 * cq;
                float a0 = sAS[cl], a1 = sAS[cl + 1];
                float b0 = sAD[cl], b1 = sAD[cl + 1];
                sl += acc[mt][nt][0] * a0 + acc[mt][nt][1] * a1;
                dl += acc[mt][nt][0] * b0 + acc[mt][nt][1] * b1;
                sh += acc[mt][nt][2] * a0 + acc[mt][nt][3] * a1;
                dh += acc[mt][nt][2] * b0 + acc[mt][nt][3] * b1;
            }
            sl += __shfl_xor_sync(FULL, sl, 1); sl += __shfl_xor_sync(FULL, sl, 2);
            dl += __shfl_xor_sync(FULL, dl, 1); dl += __shfl_xor_sync(FULL, dl, 2);
            sh += __shfl_xor_sync(FULL, sh, 1); sh += __shfl_xor_sync(FULL, sh, 2);
            dh += __shfl_xor_sync(FULL, dh, 1); dh += __shfl_xor_sync(FULL, dh, 2);
            if (cq == 0) {
                int hg = bn / C1 + 2 * wn + m;
                if (row0 < M)     { s_[(long)row0 * H1 + hg] = sl; d_[(long)row0 * H1 + hg] = dl; }
                if (row0 + 8 < M) { s_[(long)(row0 + 8) * H1 + hg] = sh; d_[(long)(row0 + 8) * H1 + hg] = dh; }
            }
        }
    }
}

// fp16 A (exact), fp32 B split -> 2-term MMA (layer 2). Fused attn epilogue
// (C2=8: each nt tile of 8 cols = one head).
template <int BM, int BN, int BK>
__global__ void __launch_bounds__(256)
k_gemm_h16(const __half* __restrict__ A, const float* __restrict__ B,
           __half* __restrict__ Cm, int M, int K, int Nc,
           const float* __restrict__ aS, const float* __restrict__ aD,
           float* __restrict__ s_, float* __restrict__ d_) {
    constexpr int KP  = BK / 2;
    constexpr int AST = BM + 8;
    constexpr int BST = BN + 8;
    __shared__ uint32_t AsB[2][KP][AST];
    __shared__ uint32_t BsB[2][KP][BST], BsS[2][KP][BST];
    __shared__ float sAS[BN], sAD[BN];
    constexpr int ALD = BM * KP / 256;   // 4
    constexpr int BLD = BN * KP / 256;   // 2
    int t = threadIdx.x;
    int lane = t & 31, wid = t >> 5;
    int wm = wid & 3, wn = wid >> 2;
    int cq = lane & 3, gq = lane >> 2;
    int bm = blockIdx.y * BM, bn = blockIdx.x * BN;
    float acc[2][4][4] = {};
    uint32_t rabg[ALD], rbbg[BLD], rbsm[BLD];

    if (t < BN) { sAS[t] = aS[bn + t]; sAD[t] = aD[bn + t]; }

    #pragma unroll
    for (int u = 0; u < ALD; u++) {
        int i = t + 256 * u;
        int r = i >> 3, kp = i & 7;
        int row = bm + r;
        int k0 = 2 * kp;
        uint32_t va = 0;
        if (row < M && k0 + 1 < K) va = *(const uint32_t*)&A[(long)row * K + k0];
        AsB[0][kp][r] = va;
    }
    #pragma unroll
    for (int u = 0; u < BLD; u++) {
        int i = t + 256 * u;
        int col = i % BN, kp = i / BN;
        int k0 = 2 * kp;
        float x0 = (k0     < K) ? B[(long)k0       * Nc + bn + col] : 0.f;
        float x1 = (k0 + 1 < K) ? B[(long)(k0 + 1) * Nc + bn + col] : 0.f;
        uint32_t bg, sm;
        split_pair(x0, x1, bg, sm);
        BsB[0][kp][col] = bg; BsS[0][kp][col] = sm;
    }
    __syncthreads();

    int nTiles = (K + BK - 1) / BK;
    for (int tile = 0; tile < nTiles; tile++) {
        int buf = tile & 1;
        int k0n = (tile + 1) * BK;
        if (tile + 1 < nTiles) {
            #pragma unroll
            for (int u = 0; u < ALD; u++) {
                int i = t + 256 * u;
                int r = i >> 3, kp = i & 7;
                int row = bm + r;
                int k0 = k0n + 2 * kp;
                uint32_t va = 0;
                if (row < M && k0 + 1 < K) va = *(const uint32_t*)&A[(long)row * K + k0];
                rabg[u] = va;
            }
            #pragma unroll
            for (int u = 0; u < BLD; u++) {
                int i = t + 256 * u;
                int col = i % BN, kp = i / BN;
                int k0 = k0n + 2 * kp;
                float x0 = (k0     < K) ? B[(long)k0       * Nc + bn + col] : 0.f;
                float x1 = (k0 + 1 < K) ? B[(long)(k0 + 1) * Nc + bn + col] : 0.f;
                split_pair(x0, x1, rbbg[u], rbsm[u]);
            }
        }
        {
            uint32_t ab[2][4];
            #pragma unroll
            for (int mt = 0; mt < 2; mt++) {
                int row = wm * 32 + mt * 16 + gq;
                ab[mt][0] = AsB[buf][cq][row];     ab[mt][1] = AsB[buf][cq][row + 8];
                ab[mt][2] = AsB[buf][cq + 4][row]; ab[mt][3] = AsB[buf][cq + 4][row + 8];
            }
            uint32_t bb[4][2], bs[4][2];
            #pragma unroll
            for (int nt = 0; nt < 4; nt++) {
                int col = wn * 32 + nt * 8 + gq;
                bb[nt][0] = BsB[buf][cq][col]; bb[nt][1] = BsB[buf][cq + 4][col];
                bs[nt][0] = BsS[buf][cq][col]; bs[nt][1] = BsS[buf][cq + 4][col];
            }
            #pragma unroll
            for (int mt = 0; mt < 2; mt++)
                #pragma unroll
                for (int nt = 0; nt < 4; nt++) {
                    mma_f16(acc[mt][nt], ab[mt], bs[nt]);
                    mma_f16(acc[mt][nt], ab[mt], bb[nt]);
                }
        }
        if (tile + 1 < nTiles) {
            __syncthreads();
            int nb = buf ^ 1;
            #pragma unroll
            for (int u = 0; u < ALD; u++) {
                int i = t + 256 * u;
                int r = i >> 3, kp = i & 7;
                AsB[nb][kp][r] = rabg[u];
            }
            #pragma unroll
            for (int u = 0; u < BLD; u++) {
                int i = t + 256 * u;
                int col = i % BN, kp = i / BN;
                BsB[nb][kp][col] = rbbg[u]; BsS[nb][kp][col] = rbsm[u];
            }
            __syncthreads();
        }
    }
    #pragma unroll
    for (int mt = 0; mt < 2; mt++) {
        int row0 = bm + wm * 32 + mt * 16 + gq;
        #pragma unroll
        for (int nt = 0; nt < 4; nt++) {
            int col = bn + wn * 32 + nt * 8 + 2 * cq;
            if (row0 < M)
                *(__half2*)&Cm[(long)row0 * Nc + col] =
                    __floats2half2_rn(acc[mt][nt][0], acc[mt][nt][1]);
            if (row0 + 8 < M)
                *(__half2*)&Cm[(long)(row0 + 8) * Nc + col] =
                    __floats2half2_rn(acc[mt][nt][2], acc[mt][nt][3]);
            // fused attention: one head per nt (8 cols)
            int cl = wn * 32 + nt * 8 + 2 * cq;
            float a0 = sAS[cl], a1 = sAS[cl + 1];
            float b0 = sAD[cl], b1 = sAD[cl + 1];
            float sl = acc[mt][nt][0] * a0 + acc[mt][nt][1] * a1;
            float dl = acc[mt][nt][0] * b0 + acc[mt][nt][1] * b1;
            float sh = acc[mt][nt][2] * a0 + acc[mt][nt][3] * a1;
            float dh = acc[mt][nt][2] * b0 + acc[mt][nt][3] * b1;
            sl += __shfl_xor_sync(FULL, sl, 1); sl += __shfl_xor_sync(FULL, sl, 2);
            dl += __shfl_xor_sync(FULL, dl, 1); dl += __shfl_xor_sync(FULL, dl, 2);
            sh += __shfl_xor_sync(FULL, sh, 1); sh += __shfl_xor_sync(FULL, sh, 2);
            dh += __shfl_xor_sync(FULL, dh, 1); dh += __shfl_xor_sync(FULL, dh, 2);
            if (cq == 0) {
                int hg = bn / C2 + 4 * wn + nt;
                if (row0 < M)     { s_[(long)row0 * H2 + hg] = sl; d_[(long)row0 * H2 + hg] = dl; }
                if (row0 + 8 < M) { s_[(long)(row0 + 8) * H2 + hg] = sh; d_[(long)(row0 + 8) * H2 + hg] = dh; }
            }
        }
    }
}

// ---------------- layer-1 aggregation: one LDG.128 per edge -----------------
__device__ __forceinline__ void acc8(float* acc, uint4 v, float w) {
    __half2* hv = reinterpret_cast<__half2*>(&v);
    #pragma unroll
    for (int q = 0; q < 4; q++) {
        float2 f = __half22float2(hv[q]);
        acc[2 * q]     += w * f.x;
        acc[2 * q + 1] += w * f.y;
    }
}

__global__ void k_agg1(const __half* __restrict__ h, const float* __restrict__ as_,
                       const float* __restrict__ ad_, const float* __restrict__ bias,
                       __half* __restrict__ out, int n0, int cnt) {
    constexpr int H = H1, D = D1;
    int warp = (blockIdx.x * blockDim.x + threadIdx.x) >> 5;
    int lane = threadIdx.x & 31;
    if (warp >= cnt) return;
    int node = n0 + warp;
    int r0 = g_rowptr[node];
    int r1 = g_rowptr[node + 1];

    float adv = (lane < H) ? ad_[node * H + lane] : 0.f;
    int myHead = (lane < 24) ? (lane >> 1) : 0;

    float acc[8] = {};
    float denom = 0.f;

    // implicit self-loop
    float wS = 0.f;
    if (lane < H) {
        wS = __expf(leaky(__ldg(as_ + (long)node * H + lane) + adv));
        denom = wS;
    }
    float eS = __shfl_sync(FULL, wS, myHead);
    if (lane < 24) {
        uint4 v = *(const uint4*)(h + (long)node * D + lane * 8);
        acc8(acc, v, eS);
    }

    int j = r0;
    for (; j + 3 < r1; j += 4) {
        int s0 = g_col[j], s1 = g_col[j + 1], s2 = g_col[j + 2], s3 = g_col[j + 3];
        float w0 = 0.f, w1 = 0.f, w2 = 0.f, w3 = 0.f;
        if (lane < H) {
            w0 = __expf(leaky(__ldg(as_ + (long)s0 * H + lane) + adv));
            w1 = __expf(leaky(__ldg(as_ + (long)s1 * H + lane) + adv));
            w2 = __expf(leaky(__ldg(as_ + (long)s2 * H + lane) + adv));
            w3 = __expf(leaky(__ldg(as_ + (long)s3 * H + lane) + adv));
            denom += (w0 + w1) + (w2 + w3);
        }
        float e0 = __shfl_sync(FULL, w0, myHead);
        float e1 = __shfl_sync(FULL, w1, myHead);
        float e2 = __shfl_sync(FULL, w2, myHead);
        float e3 = __shfl_sync(FULL, w3, myHead);
        if (lane < 24) {
            uint4 v0 = *(const uint4*)(h + (long)s0 * D + lane * 8);
            uint4 v1 = *(const uint4*)(h + (long)s1 * D + lane * 8);
            uint4 v2 = *(const uint4*)(h + (long)s2 * D + lane * 8);
            uint4 v3 = *(const uint4*)(h + (long)s3 * D + lane * 8);
            acc8(acc, v0, e0);
            acc8(acc, v1, e1);
            acc8(acc, v2, e2);
            acc8(acc, v3, e3);
        }
    }
    for (; j < r1; j++) {
        int s0 = g_col[j];
        float w0 = 0.f;
        if (lane < H) {
            w0 = __expf(leaky(__ldg(as_ + (long)s0 * H + lane) + adv));
            denom += w0;
        }
        float e0 = __shfl_sync(FULL, w0, myHead);
        if (lane < 24) {
            uint4 v0 = *(const uint4*)(h + (long)s0 * D + lane * 8);
            acc8(acc, v0, e0);
        }
    }

    float rden = __frcp_rn(denom);
    float rk = __shfl_sync(FULL, rden, myHead);
    if (lane < 24) {
        int off = lane * 8;
        const float4* bp = (const float4*)&bias[off];
        float4 b0 = bp[0], b1 = bp[1];
        float v[8];
        v[0] = acc[0] * rk + b0.x; v[1] = acc[1] * rk + b0.y;
        v[2] = acc[2] * rk + b0.z; v[3] = acc[3] * rk + b0.w;
        v[4] = acc[4] * rk + b1.x; v[5] = acc[5] * rk + b1.y;
        v[6] = acc[6] * rk + b1.z; v[7] = acc[7] * rk + b1.w;
        #pragma unroll
        for (int q = 0; q < 8; q++)
            v[q] = v[q] > 0.f ? v[q] : __expf(v[q]) - 1.f;
        uint4 pk;
        __half2* ph = reinterpret_cast<__half2*>(&pk);
        ph[0] = __floats2half2_rn(v[0], v[1]);
        ph[1] = __floats2half2_rn(v[2], v[3]);
        ph[2] = __floats2half2_rn(v[4], v[5]);
        ph[3] = __floats2half2_rn(v[6], v[7]);
        *(uint4*)(out + (long)node * D + off) = pk;
    }
}

// ---------------- layer-2 aggregation (half2 gather, fp32 out) --------------
template <int H, int C>
__global__ void k_agg(const __half* __restrict__ h, const float* __restrict__ as_,
                      const float* __restrict__ ad_, const float* __restrict__ bias,
                      float* __restrict__ out, int n0, int cnt) {
    constexpr int D = H * C;
    constexpr int PER2 = D / 64;
    int warp = (blockIdx.x * blockDim.x + threadIdx.x) >> 5;
    int lane = threadIdx.x & 31;
    if (warp >= cnt) return;
    int node = n0 + warp;
    int r0 = g_rowptr[node];
    int r1 = g_rowptr[node + 1];

    float adv = (lane < H) ? ad_[node * H + lane] : 0.f;

    float2 acc[PER2];
    #pragma unroll
    for (int i = 0; i < PER2; i++) acc[i] = make_float2(0.f, 0.f);
    float denom = 0.f;

    // implicit self-loop
    {
        float wS = 0.f;
        if (lane < H) {
            wS = __expf(leaky(__ldg(as_ + (long)node * H + lane) + adv));
            denom = wS;
        }
        const __half2* hp = (const __half2*)(h + (long)node * D);
        #pragma unroll
        for (int i = 0; i < PER2; i++) {
            int k2 = 2 * lane + 64 * i;
            int p  = lane + 32 * i;
            float wa = __shfl_sync(FULL, wS, k2 / C);
            float2 v0 = __half22float2(hp[p]);
            acc[i].x += wa * v0.x;
            acc[i].y += wa * v0.y;
        }
    }

    int j = r0;
    for (; j + 3 < r1; j += 4) {
        int s0 = g_col[j], s1 = g_col[j + 1], s2 = g_col[j + 2], s3 = g_col[j + 3];
        float w0 = 0.f, w1 = 0.f, w2 = 0.f, w3 = 0.f;
        if (lane < H) {
            w0 = __expf(leaky(__ldg(as_ + (long)s0 * H + lane) + adv));
            w1 = __expf(leaky(__ldg(as_ + (long)s1 * H + lane) + adv));
            w2 = __expf(leaky(__ldg(as_ + (long)s2 * H + lane) + adv));
            w3 = __expf(leaky(__ldg(as_ + (long)s3 * H + lane) + adv));
            denom += (w0 + w1) + (w2 + w3);
        }
        const __half2* h0 = (const __half2*)(h + (long)s0 * D);
        const __half2* h1 = (const __half2*)(h + (long)s1 * D);
        const __half2* h2 = (const __half2*)(h + (long)s2 * D);
        const __half2* h3 = (const __half2*)(h + (long)s3 * D);
        #pragma unroll
        for (int i = 0; i < PER2; i++) {
            int k2 = 2 * lane + 64 * i;
            int p  = lane + 32 * i;
            int sl = k2 / C;
            float wa = __shfl_sync(FULL, w0, sl);
            float wb = __shfl_sync(FULL, w1, sl);
            float wc = __shfl_sync(FULL, w2, sl);
            float wd = __shfl_sync(FULL, w3, sl);
            float2 v0 = __half22float2(h0[p]);
            float2 v1 = __half22float2(h1[p]);
            float2 v2 = __half22float2(h2[p]);
            float2 v3 = __half22float2(h3[p]);
            acc[i].x += wa * v0.x + wb * v1.x + wc * v2.x + wd * v3.x;
            acc[i].y += wa * v0.y + wb * v1.y + wc * v2.y + wd * v3.y;
        }
    }
    for (; j < r1; j++) {
        int s0 = g_col[j];
        float w0 = 0.f;
        if (lane < H) {
            w0 = __expf(leaky(__ldg(as_ + (long)s0 * H + lane) + adv));
            denom += w0;
        }
        const __half2* h0 = (const __half2*)(h + (long)s0 * D);
        #pragma unroll
        for (int i = 0; i < PER2; i++) {
            int k2 = 2 * lane + 64 * i;
            int p  = lane + 32 * i;
            float wa = __shfl_sync(FULL, w0, k2 / C);
            float2 v0 = __half22float2(h0[p]);
            acc[i].x += wa * v0.x;
            acc[i].y += wa * v0.y;
        }
    }

    float rden = __frcp_rn(denom);
    #pragma unroll
    for (int i = 0; i < PER2; i++) {
        int k2 = 2 * lane + 64 * i;
        float rk = __shfl_sync(FULL, rden, k2 / C);
        float2 bv = *(const float2*)&bias[k2];
        float vx = acc[i].x * rk + bv.x;
        float vy = acc[i].y * rk + bv.y;
        vx = vx > 0.f ? vx : __expf(vx) - 1.f;
        vy = vy > 0.f ? vy : __expf(vy) - 1.f;
        *(float2*)&out[(long)node * D + k2] = make_float2(vx, vy);
    }
}

// ---------------- pair scoring head ----------------
__global__ void k_pair(const float* __restrict__ x, const int* __restrict__ n1,
                       const int* __restrict__ n2, const float* __restrict__ linW,
                       const float* __restrict__ linb, float* __restrict__ y) {
    int warp = (blockIdx.x * blockDim.x + threadIdx.x) >> 5;
    int lane = threadIdx.x & 31;
    if (warp >= PAIRS) return;
    int a = n1[warp], b = n2[warp];
    float p0 = 0.f, p1 = 0.f;
    #pragma unroll
    for (int i = 0; i < 4; i++) {
        int k = lane + 32 * i;
        float xv = (k < D2) ? x[(long)a * D2 + k] : x[(long)b * D2 + (k - D2)];
        p0 += xv * linW[k * 2 + 0];
        p1 += xv * linW[k * 2 + 1];
    }
    #pragma unroll
    for (int off = 16; off; off >>= 1) {
        p0 += __shfl_xor_sync(FULL, p0, off);
        p1 += __shfl_xor_sync(FULL, p1, off);
    }
    if (lane == 0) {
        float z0 = p0 + linb[0], z1 = p1 + linb[1];
        y[warp * 2 + 0] = 1.f / (1.f + __expf(-z0));
        y[warp * 2 + 1] = 1.f / (1.f + __expf(-z1));
    }
}

// ---------------- launcher with fork/join + agg1/GEMM2 pipelining ----------
extern "C" void kernel_launch(void* const* d_in, const int* in_sizes, int n_in,
                              void* d_out, int out_size) {
    const float* features = (const float*)d_in[0];
    const int*   edge_index = (const int*)d_in[1];
    const int*   n1 = (const int*)d_in[2];
    const int*   n2 = (const int*)d_in[3];
    const float* W1 = (const float*)d_in[4];
    const float* attS1 = (const float*)d_in[5];
    const float* attD1 = (const float*)d_in[6];
    const float* b1 = (const float*)d_in[7];
    const float* W2 = (const float*)d_in[8];
    const float* attS2 = (const float*)d_in[9];
    const float* attD2 = (const float*)d_in[10];
    const float* b2 = (const float*)d_in[11];
    const float* linW = (const float*)d_in[12];
    const float* linb = (const float*)d_in[13];

    float* out  = (float*)d_out;
    float* y    = out;               // y_pred: [PAIRS, 2]
    float* xout = out + PAIRS * 2;   // x:      [NN, D2]

    int E = in_sizes[1] / 2;

    __half *p_h1, *p_x1h, *p_h2;
    float *p_as1, *p_ad1, *p_as2, *p_ad2;
    cudaGetSymbolAddress((void**)&p_h1, g_h1);
    cudaGetSymbolAddress((void**)&p_x1h, g_x1h);
    cudaGetSymbolAddress((void**)&p_h2, g_h2);
    cudaGetSymbolAddress((void**)&p_as1, g_as1);
    cudaGetSymbolAddress((void**)&p_ad1, g_ad1);
    cudaGetSymbolAddress((void**)&p_as2, g_as2);
    cudaGetSymbolAddress((void**)&p_ad2, g_ad2);

    static cudaStream_t s2 = nullptr;
    static cudaEvent_t evFork = nullptr, evJoin = nullptr, evA = nullptr, evG = nullptr;
    if (!s2) {
        cudaStreamCreateWithFlags(&s2, cudaStreamNonBlocking);
        cudaEventCreateWithFlags(&evFork, cudaEventDisableTiming);
        cudaEventCreateWithFlags(&evJoin, cudaEventDisableTiming);
        cudaEventCreateWithFlags(&evA, cudaEventDisableTiming);
        cudaEventCreateWithFlags(&evG, cudaEventDisableTiming);
    }

    int e4blocks = ((E + 3) / 4 + 255) / 256;

    // fork: CSR build on s2 overlaps GEMM1 (with fused attn) on main stream
    cudaEventRecord(evFork, 0);
    cudaStreamWaitEvent(s2, evFork, 0);

    k_init_deg<<<(NN + 255) / 256, 256, 0, s2>>>();
    k_count<<<e4blocks, 256, 0, s2>>>(edge_index, E);
    k_scan<<<1, 1024, 0, s2>>>();
    k_scatter<<<e4blocks, 256, 0, s2>>>(edge_index, E);
    cudaEventRecord(evJoin, s2);

    {
        dim3 grid(D1 / 64, (NN + 127) / 128);
        k_gemm_hs<128, 64, 16><<<grid, 256>>>(features, W1, p_h1, NN, FEA, D1,
                                              attS1, attD1, p_as1, p_ad1);
    }

    cudaStreamWaitEvent(0, evJoin, 0);

    // agg1 lo half, then pipeline: GEMM2-lo on s2 overlaps agg1 hi half
    k_agg1<<<(NHALF * 32 + 255) / 256, 256>>>(p_h1, p_as1, p_ad1, b1, p_x1h, 0, NHALF);
    cudaEventRecord(evA, 0);
    cudaStreamWaitEvent(s2, evA, 0);
    {
        dim3 grid(D2 / 64, NHALF / 128);
        k_gemm_h16<128, 64, 16><<<grid, 256, 0, s2>>>(p_x1h, W2, p_h2, NHALF, D1, D2,
                                                      attS2, attD2, p_as2, p_ad2);
    }
    cudaEventRecord(evG, s2);

    k_agg1<<<((NN - NHALF) * 32 + 255) / 256, 256>>>(p_h1, p_as1, p_ad1, b1, p_x1h, NHALF, NN - NHALF);
    {
        dim3 grid(D2 / 64, (NN - NHALF + 127) / 128);
        k_gemm_h16<128, 64, 16><<<grid, 256>>>(p_x1h + (long)NHALF * D1, W2,
                                               p_h2 + (long)NHALF * D2, NN - NHALF, D1, D2,
                                               attS2, attD2,
                                               p_as2 + (long)NHALF * H2, p_ad2 + (long)NHALF * H2);
    }
    cudaStreamWaitEvent(0, evG, 0);

    k_agg<H2, C2><<<(NN * 32 + 255) / 256, 256>>>(p_h2, p_as2, p_ad2, b2, xout, 0, NN);

    // Pair head
    k_pair<<<(PAIRS * 32 + 255) / 256, 256>>>(xout, n1, n2, linW, linb, y);
}